// round 6
// baseline (speedup 1.0000x reference)
#include <cuda_runtime.h>
#include <cuda_bf16.h>
#include <math.h>
#include <stdint.h>

#define HID 128
#define CLS 10
#define NMAX 100000
#define EMAX 1600000
#define CMAX 50000
#define GMAX 64
#define SCAN_B 256
#define MTOT (NMAX + CMAX)
#define NTILES 1024
#define TILEMAX ((NMAX + 127) / 128)   // 782

typedef unsigned long long ull;

// ---------------- scratch (device globals) -----------------------------------
__device__ __align__(256) float g_h2[(size_t)NMAX * HID];   // fp32 layer-2 output
__device__ __align__(256) float g_xc[(size_t)CMAX * HID];   // fp32 cluster means
__device__ __align__(16) uint32_t g_xb [(size_t)NMAX * 64]; // bf16 x table
__device__ __align__(16) uint32_t g_h1b[(size_t)NMAX * 64]; // bf16 h1 table
__device__ __align__(16) uint32_t g_xcb[(size_t)CMAX * 64]; // bf16 xc table
__device__ __align__(16) float2 g_bfrag[4 * 16 * 16 * 32];  // tf32 B fragments
__device__ __align__(256) float4 g_xfrag [(size_t)TILEMAX * 4096]; // tf32 A-frags of x
__device__ __align__(256) float4 g_h1frag[(size_t)TILEMAX * 4096]; // tf32 A-frags of h1
__device__ int g_off[MTOT + 1];
__device__ int g_cur[MTOT];
__device__ int g_esrt[EMAX];           // src ids sorted by dst
__device__ int g_cnodes[NMAX];         // node ids sorted by cluster

// single zeroed region: [cnt MTOT][tstate NTILES][gsum G*CLS][gcnt G]
__device__ int g_zero[MTOT + NTILES + GMAX * CLS + GMAX];
#define Zcnt   (g_zero)
#define Ztst   ((unsigned*)(g_zero + MTOT))
#define Zgsum  ((float*)(g_zero + MTOT + NTILES))
#define Zgcnt  (g_zero + MTOT + NTILES + GMAX * CLS)
#define ZTOTAL (MTOT + NTILES + GMAX * CLS + GMAX)

// ---------------- helpers ------------------------------------------------------
__device__ __forceinline__ float tf32r(float f) {
    uint32_t o;
    asm("cvt.rna.tf32.f32 %0, %1;" : "=r"(o) : "f"(f));
    return __uint_as_float(o);
}
__device__ __forceinline__ void mma8(float d[4], const unsigned a[4],
                                     unsigned b0, unsigned b1) {
    asm volatile("mma.sync.aligned.m16n8k8.row.col.f32.tf32.tf32.f32 "
                 "{%0,%1,%2,%3}, {%4,%5,%6,%7}, {%8,%9}, {%0,%1,%2,%3};"
                 : "+f"(d[0]), "+f"(d[1]), "+f"(d[2]), "+f"(d[3])
                 : "r"(a[0]), "r"(a[1]), "r"(a[2]), "r"(a[3]), "r"(b0), "r"(b1));
}
__device__ __forceinline__ void bf16acc(float4& acc, uint2 u) {
    float2 p = __bfloat1622float2(*(__nv_bfloat162*)&u.x);
    float2 q = __bfloat1622float2(*(__nv_bfloat162*)&u.y);
    acc.x += p.x; acc.y += p.y; acc.z += q.x; acc.w += q.y;
}
__device__ __forceinline__ void st_rel(unsigned* p, unsigned v) {
    asm volatile("st.release.gpu.u32 [%0], %1;" :: "l"(p), "r"(v) : "memory");
}
__device__ __forceinline__ unsigned ld_acq(unsigned* p) {
    unsigned v;
    asm volatile("ld.acquire.gpu.u32 %0, [%1];" : "=r"(v) : "l"(p) : "memory");
    return v;
}

// ---------------- mega prep: histograms + B frags + bf16 x + x A-frags ----------
__global__ void prep_count_kernel(const int* __restrict__ dst, const int* __restrict__ ca,
                                  const float* __restrict__ W0, const float* __restrict__ W1,
                                  const float* __restrict__ W2, const float* __restrict__ W3,
                                  const float* __restrict__ x, uint2* __restrict__ xb,
                                  float4* __restrict__ xfrag, int E, int n, int tiles) {
    int i = blockIdx.x * blockDim.x + threadIdx.x;
    // histogram: edges by dst, nodes by cluster
    if (i < E) atomicAdd(&Zcnt[dst[i]], 1);
    if (i < n) atomicAdd(&Zcnt[n + ca[i]], 1);
    // tf32 B fragments
    if (i < 4 * 16 * 16 * 32) {
        int lane = i & 31, nt = (i >> 5) & 15, ks = (i >> 9) & 15, mat = i >> 13;
        const float* W = (mat == 0) ? W0 : (mat == 1) ? W1 : (mat == 2) ? W2 : W3;
        int k0 = ks * 8 + (lane & 3);
        int nn = nt * 8 + (lane >> 2);
        float2 o;
        o.x = tf32r(W[(size_t)k0 * HID + nn]);
        o.y = tf32r(W[(size_t)(k0 + 4) * HID + nn]);
        g_bfrag[i] = o;
    }
    // bf16 x table
    int j = i - 4 * 16 * 16 * 32;
    if (j >= 0 && j < n * 32) {
        float4 v = *(const float4*)(x + (size_t)j * 4);
        __nv_bfloat162 lo = __floats2bfloat162_rn(v.x, v.y);
        __nv_bfloat162 hi = __floats2bfloat162_rn(v.z, v.w);
        uint2 o;
        o.x = *(uint32_t*)&lo;
        o.y = *(uint32_t*)&hi;
        xb[j] = o;
    }
    // tf32 A-fragments of x: k = float4 index into g_xfrag
    int k = j - n * 32;
    if (k >= 0 && k < tiles * 4096) {
        int lane = k & 31, mt = (k >> 5) & 7, ks = (k >> 8) & 15, tile = k >> 12;
        int r0 = tile * 128 + mt * 16 + (lane >> 2);
        int c0 = ks * 8 + (lane & 3);
        float4 o = make_float4(0, 0, 0, 0);
        if (r0 < n) {
            o.x = tf32r(x[(size_t)r0 * HID + c0]);
            o.z = tf32r(x[(size_t)r0 * HID + c0 + 4]);
        }
        if (r0 + 8 < n) {
            o.y = tf32r(x[(size_t)(r0 + 8) * HID + c0]);
            o.w = tf32r(x[(size_t)(r0 + 8) * HID + c0 + 4]);
        }
        xfrag[k] = o;
    }
}

// ---------------- single-pass decoupled-lookback exclusive scan -----------------
__global__ void scan_lookback(const int* __restrict__ in, int* __restrict__ off,
                              int* __restrict__ cur, int m) {
    __shared__ int sh[SCAN_B];
    __shared__ int s_prev;
    int b = blockIdx.x;
    int i = b * SCAN_B + threadIdx.x;
    int v = (i < m) ? in[i] : 0;
    sh[threadIdx.x] = v;
    __syncthreads();
    #pragma unroll
    for (int o = 1; o < SCAN_B; o <<= 1) {
        int t = (threadIdx.x >= o) ? sh[threadIdx.x - o] : 0;
        __syncthreads();
        sh[threadIdx.x] += t;
        __syncthreads();
    }
    int agg = sh[SCAN_B - 1];
    if (threadIdx.x == 0) {
        if (b == 0) {
            st_rel(&Ztst[0], (2u << 30) | (unsigned)agg);
            s_prev = 0;
        } else {
            st_rel(&Ztst[b], (1u << 30) | (unsigned)agg);
            int prev = 0, j = b - 1;
            while (true) {
                unsigned s;
                do { s = ld_acq(&Ztst[j]); } while ((s >> 30) == 0);
                prev += (int)(s & 0x3FFFFFFFu);
                if ((s >> 30) == 2u) break;
                j--;
            }
            st_rel(&Ztst[b], (2u << 30) | (unsigned)(prev + agg));
            s_prev = prev;
        }
    }
    __syncthreads();
    int excl = s_prev + sh[threadIdx.x] - v;
    if (i < m) {
        off[i] = excl;
        cur[i] = excl;
        if (i == m - 1) off[m] = excl + v;
    }
}

// ---------------- fill both CSR payloads ----------------------------------------
__global__ void fill_kernel(const int* __restrict__ src, const int* __restrict__ dst,
                            const int* __restrict__ ca, int E, int n) {
    int i = blockIdx.x * blockDim.x + threadIdx.x;
    if (i < E) {
        int d = dst[i];
        int pos = atomicAdd(&g_cur[d], 1);
        g_esrt[pos] = src[i];
    }
    if (i < n) {
        int c = ca[i];
        int pos = atomicAdd(&g_cur[n + c], 1);
        g_cnodes[pos - E] = i;
    }
}

// ---------------- fused node layer v2 -------------------------------------------
// gather(bf16)->smem A-frags ; MMA agg half (smem) + x half (global frags, no sync)
// epilogue: relu+norm -> smem frags -> coalesced dumps.
// MODE 1: write ofrag (tf32 A-frags) + houtb (bf16). MODE 2: write hout (fp32 rows).
#define AFRAG(ks, mt, ln) ((((ks) * 8 + (mt)) * 32 + (ln)) * 4)
#define SMEM_NODE ((16384 + 128) * 4)

template<int MODE>
__global__ __launch_bounds__(256) void node_layer_fused(
    const uint2* __restrict__ xb, const float4* __restrict__ xfrag,
    const float2* __restrict__ bfragL, const float2* __restrict__ bfragR,
    const float* __restrict__ bias,
    float4* __restrict__ ofrag, uint32_t* __restrict__ houtb,
    float* __restrict__ hout, int n)
{
    extern __shared__ float sm[];
    float* rowss = sm + 16384;
    int tid = threadIdx.x, lane = tid & 31, wid = tid >> 5;
    int n0 = blockIdx.x * 128;
    if (tid < 128) rowss[tid] = 0.0f;

    // ---- gather: warp per row, mean of bf16 neighbor rows -> smem A-frags ----
    for (int r = wid; r < 128; r += 8) {
        int node = n0 + r;
        float4 acc = make_float4(0, 0, 0, 0);
        if (node < n) {
            int off = g_off[node], end = g_off[node + 1];
            int j = off;
            for (; j + 4 <= end; j += 4) {
                int s0 = __ldg(g_esrt + j + 0);
                int s1 = __ldg(g_esrt + j + 1);
                int s2 = __ldg(g_esrt + j + 2);
                int s3 = __ldg(g_esrt + j + 3);
                uint2 u0 = __ldg(xb + (size_t)s0 * 32 + lane);
                uint2 u1 = __ldg(xb + (size_t)s1 * 32 + lane);
                uint2 u2 = __ldg(xb + (size_t)s2 * 32 + lane);
                uint2 u3 = __ldg(xb + (size_t)s3 * 32 + lane);
                bf16acc(acc, u0); bf16acc(acc, u1);
                bf16acc(acc, u2); bf16acc(acc, u3);
            }
            for (; j < end; j++) {
                int s = __ldg(g_esrt + j);
                bf16acc(acc, __ldg(xb + (size_t)s * 32 + lane));
            }
            float inv = (end > off) ? 1.0f / (float)(end - off) : 0.0f;
            acc.x *= inv; acc.y *= inv; acc.z *= inv; acc.w *= inv;
        }
        int mt = r >> 4, w = r & 15, hi = w >> 3, wr = w & 7;
        int comp = 2 * (lane & 1) + hi;
        int kk = lane >> 1;
        float v[4] = {acc.x, acc.y, acc.z, acc.w};
        #pragma unroll
        for (int q = 0; q < 4; q++)
            sm[AFRAG(kk, mt, (wr << 2) | q) + comp] = tf32r(v[q]);
    }
    __syncthreads();

    // ---- MMA phase: no syncthreads inside ----
    int warp_m = wid >> 2, warp_n = wid & 3;
    float d[4][4][4] = {};

    // agg half: A from smem frags
    #pragma unroll 2
    for (int ks = 0; ks < 16; ks++) {
        unsigned a[4][4];
        #pragma unroll
        for (int t = 0; t < 4; t++) {
            float4 v = *(float4*)&sm[AFRAG(ks, warp_m * 4 + t, lane)];
            a[t][0] = __float_as_uint(v.x); a[t][1] = __float_as_uint(v.y);
            a[t][2] = __float_as_uint(v.z); a[t][3] = __float_as_uint(v.w);
        }
        #pragma unroll
        for (int u = 0; u < 4; u++) {
            float2 bv = __ldg(&bfragL[(size_t)(ks * 16 + warp_n * 4 + u) * 32 + lane]);
            unsigned b0 = __float_as_uint(bv.x), b1 = __float_as_uint(bv.y);
            #pragma unroll
            for (int t = 0; t < 4; t++) mma8(d[t][u], a[t], b0, b1);
        }
    }
    // x half: A from global frags (coalesced __ldg)
    const float4* xf = xfrag + (size_t)blockIdx.x * 4096;
    #pragma unroll 2
    for (int ks = 0; ks < 16; ks++) {
        unsigned a[4][4];
        #pragma unroll
        for (int t = 0; t < 4; t++) {
            float4 v = __ldg(&xf[ks * 256 + (warp_m * 4 + t) * 32 + lane]);
            a[t][0] = __float_as_uint(v.x); a[t][1] = __float_as_uint(v.y);
            a[t][2] = __float_as_uint(v.z); a[t][3] = __float_as_uint(v.w);
        }
        #pragma unroll
        for (int u = 0; u < 4; u++) {
            float2 bv = __ldg(&bfragR[(size_t)(ks * 16 + warp_n * 4 + u) * 32 + lane]);
            unsigned b0 = __float_as_uint(bv.x), b1 = __float_as_uint(bv.y);
            #pragma unroll
            for (int t = 0; t < 4; t++) mma8(d[t][u], a[t], b0, b1);
        }
    }

    // ---- epilogue: bias+relu, row sum-of-squares ----
    float2 bb[4];
    #pragma unroll
    for (int u = 0; u < 4; u++)
        bb[u] = *(const float2*)(bias + warp_n * 32 + u * 8 + (lane & 3) * 2);

    #pragma unroll
    for (int t = 0; t < 4; t++) {
        float ss0 = 0, ss1 = 0;
        #pragma unroll
        for (int u = 0; u < 4; u++) {
            float c0 = fmaxf(d[t][u][0] + bb[u].x, 0.0f);
            float c1 = fmaxf(d[t][u][1] + bb[u].y, 0.0f);
            float c2 = fmaxf(d[t][u][2] + bb[u].x, 0.0f);
            float c3 = fmaxf(d[t][u][3] + bb[u].y, 0.0f);
            ss0 += c0 * c0 + c1 * c1;
            ss1 += c2 * c2 + c3 * c3;
            d[t][u][0] = c0; d[t][u][1] = c1; d[t][u][2] = c2; d[t][u][3] = c3;
        }
        int lr = warp_m * 64 + t * 16 + (lane >> 2);
        atomicAdd(&rowss[lr], ss0);
        atomicAdd(&rowss[lr + 8], ss1);
    }
    __syncthreads();   // rowss ready AND all smem agg-frag reads done

    // normalize and write back into smem frag layout (overwrites agg frags)
    #pragma unroll
    for (int t = 0; t < 4; t++) {
        int lr = warp_m * 64 + t * 16 + (lane >> 2);
        float rn0 = rsqrtf(rowss[lr]);
        float rn1 = rsqrtf(rowss[lr + 8]);
        int mt = warp_m * 4 + t;
        int flane = (lane >> 2) * 4 + 2 * (lane & 1);
        int ch2 = ((lane >> 1) & 1) * 2;
        #pragma unroll
        for (int u = 0; u < 4; u++) {
            int ks = warp_n * 4 + u;
            float* p = &sm[AFRAG(ks, mt, flane) + ch2];
            p[0] = tf32r(d[t][u][0] * rn0);
            p[1] = tf32r(d[t][u][2] * rn1);
            p[4] = tf32r(d[t][u][1] * rn0);
            p[5] = tf32r(d[t][u][3] * rn1);
        }
    }
    __syncthreads();

    if (MODE == 1) {
        // coalesced frag dump
        #pragma unroll
        for (int e = 0; e < 16; e++) {
            int f = tid + e * 256;
            ofrag[(size_t)blockIdx.x * 4096 + f] = *(float4*)&sm[f * 4];
        }
        // bf16 row-major dump
        #pragma unroll
        for (int e = 0; e < 32; e++) {
            int p = tid + e * 256;
            int r = p >> 6, cp = p & 63;
            int node = n0 + r;
            if (node >= n) continue;
            int c = cp * 2;
            int ks = c >> 3, mt = r >> 4;
            int fl = (r & 7) * 4 + (c & 3);
            int comp = 2 * ((c >> 2) & 1) + ((r >> 3) & 1);
            float v0 = sm[AFRAG(ks, mt, fl) + comp];
            float v1 = sm[AFRAG(ks, mt, fl + 1) + comp];
            __nv_bfloat162 bh = __floats2bfloat162_rn(v0, v1);
            houtb[(size_t)node * 64 + cp] = *(uint32_t*)&bh;
        }
    } else {
        // fp32 row-major dump (coalesced float4)
        #pragma unroll
        for (int e = 0; e < 16; e++) {
            int p = tid + e * 256;
            int r = p >> 5, q = p & 31;
            int node = n0 + r;
            if (node >= n) continue;
            int c = q * 4;
            int ks = c >> 3, mt = r >> 4;
            int fl = (r & 7) * 4;
            int cr = (q & 1) * 2 + ((r >> 3) & 1);
            float4 o;
            o.x = sm[AFRAG(ks, mt, fl + 0) + cr];
            o.y = sm[AFRAG(ks, mt, fl + 1) + cr];
            o.z = sm[AFRAG(ks, mt, fl + 2) + cr];
            o.w = sm[AFRAG(ks, mt, fl + 3) + cr];
            *(float4*)&hout[(size_t)node * HID + c] = o;
        }
    }
}

// ---------------- cluster mean: warp per cluster --------------------------------
__global__ void xc_kernel(int n, int E, int Cc) {
    int w = (int)(((unsigned)blockIdx.x * blockDim.x + threadIdx.x) >> 5);
    if (w >= Cc) return;
    int lane = threadIdx.x & 31;
    int mb = g_off[n + w] - E, me = g_off[n + w + 1] - E;
    float4 acc = make_float4(0, 0, 0, 0);
    for (int mi = mb; mi < me; mi++) {
        int node = g_cnodes[mi];
        float4 v = *(const float4*)(g_h2 + (size_t)node * HID + lane * 4);
        acc.x += v.x; acc.y += v.y; acc.z += v.z; acc.w += v.w;
    }
    float inv = (me > mb) ? 1.0f / (float)(me - mb) : 0.0f;
    acc.x *= inv; acc.y *= inv; acc.z *= inv; acc.w *= inv;
    *(float4*)(g_xc + (size_t)w * HID + lane * 4) = acc;
    __nv_bfloat162 lo = __floats2bfloat162_rn(acc.x, acc.y);
    __nv_bfloat162 hi = __floats2bfloat162_rn(acc.z, acc.w);
    uint2 o;
    o.x = *(uint32_t*)&lo;
    o.y = *(uint32_t*)&hi;
    *(uint2*)&g_xcb[(size_t)w * 64 + lane * 2] = o;
}

// ---------------- fused cluster layer: SMEM-hash dedup + MLP-4 gather -----------
__global__ __launch_bounds__(256) void cluster_fused_kernel(
    const float* __restrict__ Wl, const float* __restrict__ Wr,
    const float* __restrict__ b, const int* __restrict__ ca,
    const int* __restrict__ bp, int n, int E, int Cc)
{
    __shared__ float WlS[HID * CLS];
    __shared__ float WrS[HID * CLS];
    __shared__ float bS[CLS];
    __shared__ int hsh[8][512];

    int tid = threadIdx.x;
    int lane = tid & 31, wid = tid >> 5;

    for (int i = tid; i < HID * CLS; i += blockDim.x) {
        WlS[i] = Wl[i];
        WrS[i] = Wr[i];
    }
    if (tid < CLS) bS[tid] = b[tid];
    for (int i = lane; i < 512; i += 32) hsh[wid][i] = 0;
    __syncthreads();

    int w = (int)(((unsigned)blockIdx.x * blockDim.x + tid) >> 5);
    if (w >= Cc) return;

    const uint2* xcb = (const uint2*)g_xcb;
    float4 acc = make_float4(0, 0, 0, 0);
    int nuniq = 0;
    int mb = g_off[n + w] - E, me = g_off[n + w + 1] - E;
    for (int mi = mb; mi < me; mi++) {
        int node = g_cnodes[mi];
        int eb = g_off[node], ee = g_off[node + 1];
        for (int j0 = eb; j0 < ee; j0 += 32) {
            int j = j0 + lane;
            int isnew = 0, cu = 0;
            if (j < ee) {
                int s = g_esrt[j];
                cu = __ldg(ca + s);
                int key = cu + 1;
                unsigned h = ((unsigned)cu * 2654435761u) >> 23;
                h &= 511;
                while (true) {
                    int old = atomicCAS(&hsh[wid][h], 0, key);
                    if (old == 0) { isnew = 1; break; }
                    if (old == key) break;
                    h = (h + 1) & 511;
                }
            }
            unsigned m = __ballot_sync(0xffffffffu, isnew);
            nuniq += __popc(m);
            while (m) {
                int b0 = __ffs(m) - 1;             m &= m - 1;
                int b1 = m ? __ffs(m) - 1 : 32; if (b1 < 32) m &= m - 1;
                int b2 = m ? __ffs(m) - 1 : 32; if (b2 < 32) m &= m - 1;
                int b3 = m ? __ffs(m) - 1 : 32; if (b3 < 32) m &= m - 1;
                int c0 = __shfl_sync(0xffffffffu, cu, b0);
                int c1 = __shfl_sync(0xffffffffu, cu, b1 & 31);
                int c2 = __shfl_sync(0xffffffffu, cu, b2 & 31);
                int c3 = __shfl_sync(0xffffffffu, cu, b3 & 31);
                uint2 u0 = __ldg(xcb + (size_t)c0 * 32 + lane);
                uint2 u1 = make_uint2(0, 0), u2 = make_uint2(0, 0), u3 = make_uint2(0, 0);
                if (b1 < 32) u1 = __ldg(xcb + (size_t)c1 * 32 + lane);
                if (b2 < 32) u2 = __ldg(xcb + (size_t)c2 * 32 + lane);
                if (b3 < 32) u3 = __ldg(xcb + (size_t)c3 * 32 + lane);
                bf16acc(acc, u0);
                if (b1 < 32) bf16acc(acc, u1);
                if (b2 < 32) bf16acc(acc, u2);
                if (b3 < 32) bf16acc(acc, u3);
            }
        }
    }
    float inv = nuniq > 0 ? 1.0f / (float)nuniq : 0.0f;
    float4 a = make_float4(acc.x * inv, acc.y * inv, acc.z * inv, acc.w * inv);
    float4 xv = *(const float4*)(g_xc + (size_t)w * HID + lane * 4);

    float c[CLS];
    int k0 = lane * 4;
    #pragma unroll
    for (int j = 0; j < CLS; j++) {
        float s = a.x * WlS[(k0 + 0) * CLS + j] + xv.x * WrS[(k0 + 0) * CLS + j];
        s += a.y * WlS[(k0 + 1) * CLS + j] + xv.y * WrS[(k0 + 1) * CLS + j];
        s += a.z * WlS[(k0 + 2) * CLS + j] + xv.z * WrS[(k0 + 2) * CLS + j];
        s += a.w * WlS[(k0 + 3) * CLS + j] + xv.w * WrS[(k0 + 3) * CLS + j];
        c[j] = s;
    }
    #pragma unroll
    for (int j = 0; j < CLS; j++) {
        #pragma unroll
        for (int off = 16; off; off >>= 1)
            c[j] += __shfl_xor_sync(0xffffffffu, c[j], off);
    }
    float ss = 0.0f;
    #pragma unroll
    for (int j = 0; j < CLS; j++) { c[j] += bS[j]; ss += c[j] * c[j]; }
    float rn = rsqrtf(ss);
    int g = __ldg(bp + w);
    if (lane < CLS) atomicAdd(&Zgsum[g * CLS + lane], c[lane] * rn);
    if (lane == 0) atomicAdd(&Zgcnt[g], 1);
}

__global__ void final_kernel(float* __restrict__ out, int G) {
    int g = blockIdx.x * blockDim.x + threadIdx.x;
    if (g >= G) return;
    int cnt = Zgcnt[g];
    float inv = cnt > 0 ? 1.0f / (float)cnt : 0.0f;
    float v[CLS];
    float mx = -1e30f;
    #pragma unroll
    for (int j = 0; j < CLS; j++) { v[j] = Zgsum[g * CLS + j] * inv; mx = fmaxf(mx, v[j]); }
    float s = 0.0f;
    #pragma unroll
    for (int j = 0; j < CLS; j++) s += expf(v[j] - mx);
    float lse = logf(s) + mx;
    #pragma unroll
    for (int j = 0; j < CLS; j++) out[g * CLS + j] = v[j] - lse;
}

// ---------------- launch ---------------------------------------------------------
extern "C" void kernel_launch(void* const* d_in, const int* in_sizes, int n_in,
                              void* d_out, int out_size) {
    const float* x     = (const float*)d_in[0];
    const float* Wl_in = (const float*)d_in[1];
    const float* Wr_in = (const float*)d_in[2];
    const float* b_in  = (const float*)d_in[3];
    const float* Wl_h  = (const float*)d_in[4];
    const float* Wr_h  = (const float*)d_in[5];
    const float* b_h   = (const float*)d_in[6];
    const float* Wl_o  = (const float*)d_in[7];
    const float* Wr_o  = (const float*)d_in[8];
    const float* b_o   = (const float*)d_in[9];
    const int* esrc = (const int*)d_in[10];
    const int* edst = (const int*)d_in[11];
    const int* ca   = (const int*)d_in[12];
    const int* bp   = (const int*)d_in[13];

    int n  = in_sizes[0] / HID;
    int E  = in_sizes[10];
    int Cc = in_sizes[13];
    int G  = out_size / CLS;
    int m  = n + Cc;
    int tiles = (n + 127) / 128;
    float* out = (float*)d_out;

    void *p_zero, *p_off, *p_cur, *p_h2, *p_xb, *p_h1b, *p_bfrag, *p_xfrag, *p_h1frag;
    cudaGetSymbolAddress(&p_zero,   g_zero);
    cudaGetSymbolAddress(&p_off,    g_off);
    cudaGetSymbolAddress(&p_cur,    g_cur);
    cudaGetSymbolAddress(&p_h2,     g_h2);
    cudaGetSymbolAddress(&p_xb,     g_xb);
    cudaGetSymbolAddress(&p_h1b,    g_h1b);
    cudaGetSymbolAddress(&p_bfrag,  g_bfrag);
    cudaGetSymbolAddress(&p_xfrag,  g_xfrag);
    cudaGetSymbolAddress(&p_h1frag, g_h1frag);

    cudaFuncSetAttribute(node_layer_fused<1>,
                         cudaFuncAttributeMaxDynamicSharedMemorySize, SMEM_NODE);
    cudaFuncSetAttribute(node_layer_fused<2>,
                         cudaFuncAttributeMaxDynamicSharedMemorySize, SMEM_NODE);

    cudaMemsetAsync(p_zero, 0, (size_t)ZTOTAL * sizeof(int));

    // mega prep: histograms + B frags + bf16 x + x A-frags
    int pthreads = 4 * 16 * 16 * 32 + n * 32 + tiles * 4096;
    if (pthreads < E) pthreads = E;
    prep_count_kernel<<<(pthreads + 255) / 256, 256>>>(
        edst, ca, Wl_in, Wr_in, Wl_h, Wr_h, x,
        (uint2*)p_xb, (float4*)p_xfrag, E, n, tiles);

    int nb = (m + SCAN_B - 1) / SCAN_B;
    scan_lookback<<<nb, SCAN_B>>>((const int*)p_zero, (int*)p_off, (int*)p_cur, m);

    int cover = (E > n) ? E : n;
    fill_kernel<<<(cover + 255) / 256, 256>>>(esrc, edst, ca, E, n);

    const float2* bfrag = (const float2*)p_bfrag;

    // layer 1: gather bf16 x, self from x A-frags; out: h1 frags + h1 bf16
    node_layer_fused<1><<<tiles, 256, SMEM_NODE>>>(
        (const uint2*)p_xb, (const float4*)p_xfrag,
        bfrag, bfrag + 16 * 16 * 32, b_in,
        (float4*)p_h1frag, (uint32_t*)p_h1b, nullptr, n);
    // layer 2: gather bf16 h1, self from h1 frags; out: h2 fp32 rows
    node_layer_fused<2><<<tiles, 256, SMEM_NODE>>>(
        (const uint2*)p_h1b, (const float4*)p_h1frag,
        bfrag + 2 * 16 * 16 * 32, bfrag + 3 * 16 * 16 * 32, b_h,
        nullptr, nullptr, (float*)p_h2, n);

    xc_kernel<<<(Cc + 7) / 8, 256>>>(n, E, Cc);
    cluster_fused_kernel<<<(Cc + 7) / 8, 256>>>(Wl_o, Wr_o, b_o, ca, bp, n, E, Cc);

    final_kernel<<<(G + 63) / 64, 64>>>(out, G);
}

// round 7
// speedup vs baseline: 1.2966x; 1.2966x over previous
#include <cuda_runtime.h>
#include <cuda_bf16.h>
#include <math.h>
#include <stdint.h>

#define HID 128
#define CLS 10
#define NMAX 100000
#define EMAX 1600000
#define CMAX 50000
#define GMAX 64
#define SCAN_B 256
#define MTOT (NMAX + CMAX)
#define NTILES 1024

typedef unsigned long long ull;

// ---------------- scratch (device globals) -----------------------------------
__device__ __align__(256) float g_xc[(size_t)CMAX * HID];   // fp32 cluster means
__device__ __align__(16) uint32_t g_xb [(size_t)NMAX * 64]; // bf16 x
__device__ __align__(16) uint32_t g_h1b[(size_t)NMAX * 64]; // bf16 h1
__device__ __align__(16) uint32_t g_h2b[(size_t)NMAX * 64]; // bf16 h2
__device__ __align__(16) uint32_t g_xcb[(size_t)CMAX * 64]; // bf16 xc
__device__ __align__(16) float2 g_bfrag[2 * 32 * 16 * 32];  // tf32 B frags (2 layers x 32 ks)
__device__ int g_off[MTOT + 1];
__device__ int g_cur[MTOT];
__device__ int g_esrt[EMAX];
__device__ int g_cnodes[NMAX];

// single zeroed region
__device__ int g_zero[MTOT + NTILES + GMAX * CLS + GMAX];
#define Zcnt   (g_zero)
#define Ztst   ((unsigned*)(g_zero + MTOT))
#define Zgsum  ((float*)(g_zero + MTOT + NTILES))
#define Zgcnt  (g_zero + MTOT + NTILES + GMAX * CLS)
#define ZTOTAL (MTOT + NTILES + GMAX * CLS + GMAX)

// ---------------- helpers ------------------------------------------------------
__device__ __forceinline__ float tf32r(float f) {
    uint32_t o;
    asm("cvt.rna.tf32.f32 %0, %1;" : "=r"(o) : "f"(f));
    return __uint_as_float(o);
}
__device__ __forceinline__ void mma8(float d[4], const unsigned a[4],
                                     unsigned b0, unsigned b1) {
    asm volatile("mma.sync.aligned.m16n8k8.row.col.f32.tf32.tf32.f32 "
                 "{%0,%1,%2,%3}, {%4,%5,%6,%7}, {%8,%9}, {%0,%1,%2,%3};"
                 : "+f"(d[0]), "+f"(d[1]), "+f"(d[2]), "+f"(d[3])
                 : "r"(a[0]), "r"(a[1]), "r"(a[2]), "r"(a[3]), "r"(b0), "r"(b1));
}
__device__ __forceinline__ void bf16acc(float4& acc, uint2 u) {
    float2 p = __bfloat1622float2(*(__nv_bfloat162*)&u.x);
    float2 q = __bfloat1622float2(*(__nv_bfloat162*)&u.y);
    acc.x += p.x; acc.y += p.y; acc.z += q.x; acc.w += q.y;
}
__device__ __forceinline__ void st_rel(unsigned* p, unsigned v) {
    asm volatile("st.release.gpu.u32 [%0], %1;" :: "l"(p), "r"(v) : "memory");
}
__device__ __forceinline__ unsigned ld_acq(unsigned* p) {
    unsigned v;
    asm volatile("ld.acquire.gpu.u32 %0, [%1];" : "=r"(v) : "l"(p) : "memory");
    return v;
}

// frag layout: 32 ksteps x 4 mtiles x 32 lanes x 4 comps, ks-stride padded (+4)
#define AFRAG(ks, mt, ln) ((ks) * 516 + ((mt) * 32 + (ln)) * 4)
__device__ __forceinline__ int fragidx(int r, int c) {
    return AFRAG(c >> 3, r >> 4, ((r & 7) << 2) | (c & 3))
         + 2 * ((c >> 2) & 1) + ((r >> 3) & 1);
}
#define SMEM_NODE ((32 * 516 + 64) * 4)

// ---------------- prep: histograms + B frags + bf16 x ---------------------------
__global__ void prep_count_kernel(const int* __restrict__ dst, const int* __restrict__ ca,
                                  const float* __restrict__ Wl0, const float* __restrict__ Wr0,
                                  const float* __restrict__ Wl1, const float* __restrict__ Wr1,
                                  const float* __restrict__ x, uint2* __restrict__ xb,
                                  int E, int n) {
    int i = blockIdx.x * blockDim.x + threadIdx.x;
    if (i < E) atomicAdd(&Zcnt[dst[i]], 1);
    if (i < n) atomicAdd(&Zcnt[n + ca[i]], 1);
    if (i < 2 * 32 * 16 * 32) {
        int lane = i & 31, nt = (i >> 5) & 15, ks = (i >> 9) & 31, layer = i >> 14;
        const float* W = layer ? (ks < 16 ? Wl1 : Wr1) : (ks < 16 ? Wl0 : Wr0);
        int kl = ks & 15;
        int k0 = kl * 8 + (lane & 3);
        int nn = nt * 8 + (lane >> 2);
        float2 o;
        o.x = tf32r(W[(size_t)k0 * HID + nn]);
        o.y = tf32r(W[(size_t)(k0 + 4) * HID + nn]);
        g_bfrag[i] = o;
    }
    int j = i - 2 * 32 * 16 * 32;
    if (j >= 0 && j < n * 32) {
        float4 v = *(const float4*)(x + (size_t)j * 4);
        __nv_bfloat162 lo = __floats2bfloat162_rn(v.x, v.y);
        __nv_bfloat162 hi = __floats2bfloat162_rn(v.z, v.w);
        uint2 o;
        o.x = *(uint32_t*)&lo;
        o.y = *(uint32_t*)&hi;
        xb[j] = o;
    }
}

// ---------------- single-pass decoupled-lookback exclusive scan -----------------
__global__ void scan_lookback(const int* __restrict__ in, int* __restrict__ off,
                              int* __restrict__ cur, int m) {
    __shared__ int sh[SCAN_B];
    __shared__ int s_prev;
    int b = blockIdx.x;
    int i = b * SCAN_B + threadIdx.x;
    int v = (i < m) ? in[i] : 0;
    sh[threadIdx.x] = v;
    __syncthreads();
    #pragma unroll
    for (int o = 1; o < SCAN_B; o <<= 1) {
        int t = (threadIdx.x >= o) ? sh[threadIdx.x - o] : 0;
        __syncthreads();
        sh[threadIdx.x] += t;
        __syncthreads();
    }
    int agg = sh[SCAN_B - 1];
    if (threadIdx.x == 0) {
        if (b == 0) {
            st_rel(&Ztst[0], (2u << 30) | (unsigned)agg);
            s_prev = 0;
        } else {
            st_rel(&Ztst[b], (1u << 30) | (unsigned)agg);
            int prev = 0, j = b - 1;
            while (true) {
                unsigned s;
                do { s = ld_acq(&Ztst[j]); } while ((s >> 30) == 0);
                prev += (int)(s & 0x3FFFFFFFu);
                if ((s >> 30) == 2u) break;
                j--;
            }
            st_rel(&Ztst[b], (2u << 30) | (unsigned)(prev + agg));
            s_prev = prev;
        }
    }
    __syncthreads();
    int excl = s_prev + sh[threadIdx.x] - v;
    if (i < m) {
        off[i] = excl;
        cur[i] = excl;
        if (i == m - 1) off[m] = excl + v;
    }
}

// ---------------- fill both CSR payloads ----------------------------------------
__global__ void fill_kernel(const int* __restrict__ src, const int* __restrict__ dst,
                            const int* __restrict__ ca, int E, int n) {
    int i = blockIdx.x * blockDim.x + threadIdx.x;
    if (i < E) {
        int d = dst[i];
        int pos = atomicAdd(&g_cur[d], 1);
        g_esrt[pos] = src[i];
    }
    if (i < n) {
        int c = ca[i];
        int pos = atomicAdd(&g_cur[n + c], 1);
        g_cnodes[pos - E] = i;
    }
}

// ---------------- fused node layer v3: 64-row tile, 3 blocks/SM ------------------
// frags ks 0..15 = neighbor-mean (gather), ks 16..31 = self; one MMA loop.
template<int SELF_BF16>
__global__ __launch_bounds__(256, 3) void node_layer(
    const uint2* __restrict__ gtab, const float* __restrict__ selff,
    const uint2* __restrict__ selfb, const float2* __restrict__ bfrag,
    const float* __restrict__ bias, uint32_t* __restrict__ houtb, int n)
{
    extern __shared__ float sm[];
    float* rowss = sm + 32 * 516;
    int tid = threadIdx.x, lane = tid & 31, wid = tid >> 5;
    int n0 = blockIdx.x * 64;
    if (tid < 64) rowss[tid] = 0.0f;

    // ---- self rows -> frags ks 16..31 (warp per row, coalesced) ----
    for (int r = wid; r < 64; r += 8) {
        int node = n0 + r;
        float4 v = make_float4(0, 0, 0, 0);
        if (node < n) {
            if (SELF_BF16) {
                uint2 u = __ldg(selfb + (size_t)node * 32 + lane);
                float2 p = __bfloat1622float2(*(__nv_bfloat162*)&u.x);
                float2 q = __bfloat1622float2(*(__nv_bfloat162*)&u.y);
                v = make_float4(p.x, p.y, q.x, q.y);
            } else {
                v = *(const float4*)(selff + (size_t)node * HID + lane * 4);
            }
        }
        int base = AFRAG(16 + (lane >> 1), r >> 4, (r & 7) << 2);
        int comp = 2 * (lane & 1) + ((r >> 3) & 1);
        sm[base + 0 + comp]  = tf32r(v.x);
        sm[base + 4 + comp]  = tf32r(v.y);
        sm[base + 8 + comp]  = tf32r(v.z);
        sm[base + 12 + comp] = tf32r(v.w);
    }

    // ---- gather: warp per row, MLP-8 neighbor-mean -> frags ks 0..15 ----
    for (int r = wid; r < 64; r += 8) {
        int node = n0 + r;
        float4 acc = make_float4(0, 0, 0, 0);
        if (node < n) {
            int off = g_off[node], end = g_off[node + 1];
            int j = off;
            for (; j + 8 <= end; j += 8) {
                int s[8];
                uint2 u[8];
                #pragma unroll
                for (int q = 0; q < 8; q++) s[q] = __ldg(g_esrt + j + q);
                #pragma unroll
                for (int q = 0; q < 8; q++) u[q] = __ldg(gtab + (size_t)s[q] * 32 + lane);
                #pragma unroll
                for (int q = 0; q < 8; q++) bf16acc(acc, u[q]);
            }
            for (; j + 2 <= end; j += 2) {
                int s0 = __ldg(g_esrt + j), s1 = __ldg(g_esrt + j + 1);
                uint2 u0 = __ldg(gtab + (size_t)s0 * 32 + lane);
                uint2 u1 = __ldg(gtab + (size_t)s1 * 32 + lane);
                bf16acc(acc, u0);
                bf16acc(acc, u1);
            }
            if (j < end) {
                int s = __ldg(g_esrt + j);
                bf16acc(acc, __ldg(gtab + (size_t)s * 32 + lane));
            }
            float inv = (end > off) ? 1.0f / (float)(end - off) : 0.0f;
            acc.x *= inv; acc.y *= inv; acc.z *= inv; acc.w *= inv;
        }
        int base = AFRAG(lane >> 1, r >> 4, (r & 7) << 2);
        int comp = 2 * (lane & 1) + ((r >> 3) & 1);
        sm[base + 0 + comp]  = tf32r(acc.x);
        sm[base + 4 + comp]  = tf32r(acc.y);
        sm[base + 8 + comp]  = tf32r(acc.z);
        sm[base + 12 + comp] = tf32r(acc.w);
    }
    __syncthreads();

    // ---- MMA: 32 ksteps, no syncs ----
    int warp_m = wid >> 2, warp_n = wid & 3;
    float d[2][4][4] = {};
    #pragma unroll 4
    for (int ks = 0; ks < 32; ks++) {
        unsigned a[2][4];
        #pragma unroll
        for (int t = 0; t < 2; t++) {
            float4 v = *(float4*)&sm[AFRAG(ks, warp_m * 2 + t, lane)];
            a[t][0] = __float_as_uint(v.x); a[t][1] = __float_as_uint(v.y);
            a[t][2] = __float_as_uint(v.z); a[t][3] = __float_as_uint(v.w);
        }
        #pragma unroll
        for (int u = 0; u < 4; u++) {
            float2 bv = __ldg(&bfrag[(size_t)(ks * 16 + warp_n * 4 + u) * 32 + lane]);
            unsigned b0 = __float_as_uint(bv.x), b1 = __float_as_uint(bv.y);
            mma8(d[0][u], a[0], b0, b1);
            mma8(d[1][u], a[1], b0, b1);
        }
    }

    // ---- epilogue: bias + relu + cross-warp row norm ----
    float2 bb[4];
    #pragma unroll
    for (int u = 0; u < 4; u++)
        bb[u] = *(const float2*)(bias + warp_n * 32 + u * 8 + (lane & 3) * 2);

    #pragma unroll
    for (int t = 0; t < 2; t++) {
        float ss0 = 0, ss1 = 0;
        #pragma unroll
        for (int u = 0; u < 4; u++) {
            float c0 = fmaxf(d[t][u][0] + bb[u].x, 0.0f);
            float c1 = fmaxf(d[t][u][1] + bb[u].y, 0.0f);
            float c2 = fmaxf(d[t][u][2] + bb[u].x, 0.0f);
            float c3 = fmaxf(d[t][u][3] + bb[u].y, 0.0f);
            ss0 += c0 * c0 + c1 * c1;
            ss1 += c2 * c2 + c3 * c3;
            d[t][u][0] = c0; d[t][u][1] = c1; d[t][u][2] = c2; d[t][u][3] = c3;
        }
        int lr = (warp_m * 2 + t) * 16 + (lane >> 2);
        atomicAdd(&rowss[lr], ss0);
        atomicAdd(&rowss[lr + 8], ss1);
    }
    __syncthreads();   // rowss ready; all MMA frag reads complete

    // normalize, write back into frag layout (overwrites inputs)
    #pragma unroll
    for (int t = 0; t < 2; t++) {
        int r1 = (warp_m * 2 + t) * 16 + (lane >> 2);
        float rn0 = rsqrtf(rowss[r1]);
        float rn1 = rsqrtf(rowss[r1 + 8]);
        #pragma unroll
        for (int u = 0; u < 4; u++) {
            int c1 = warp_n * 32 + u * 8 + (lane & 3) * 2;
            sm[fragidx(r1, c1)]         = d[t][u][0] * rn0;
            sm[fragidx(r1, c1 + 1)]     = d[t][u][1] * rn0;
            sm[fragidx(r1 + 8, c1)]     = d[t][u][2] * rn1;
            sm[fragidx(r1 + 8, c1 + 1)] = d[t][u][3] * rn1;
        }
    }
    __syncthreads();

    // coalesced bf16 dump
    #pragma unroll
    for (int e = 0; e < 16; e++) {
        int p = tid + e * 256;
        int r = p >> 6, cp = p & 63;
        int node = n0 + r;
        if (node >= n) continue;
        int c = cp * 2;
        float v0 = sm[fragidx(r, c)];
        float v1 = sm[fragidx(r, c + 1)];
        __nv_bfloat162 bh = __floats2bfloat162_rn(v0, v1);
        houtb[(size_t)node * 64 + cp] = *(uint32_t*)&bh;
    }
}

// ---------------- cluster mean from bf16 h2: warp per cluster -------------------
__global__ void xc_kernel(const uint2* __restrict__ h2b, int n, int E, int Cc) {
    int w = (int)(((unsigned)blockIdx.x * blockDim.x + threadIdx.x) >> 5);
    if (w >= Cc) return;
    int lane = threadIdx.x & 31;
    int mb = g_off[n + w] - E, me = g_off[n + w + 1] - E;
    float4 acc = make_float4(0, 0, 0, 0);
    int mi = mb;
    for (; mi + 2 <= me; mi += 2) {
        int n0 = g_cnodes[mi], n1 = g_cnodes[mi + 1];
        uint2 u0 = __ldg(h2b + (size_t)n0 * 32 + lane);
        uint2 u1 = __ldg(h2b + (size_t)n1 * 32 + lane);
        bf16acc(acc, u0);
        bf16acc(acc, u1);
    }
    if (mi < me) {
        int n0 = g_cnodes[mi];
        bf16acc(acc, __ldg(h2b + (size_t)n0 * 32 + lane));
    }
    float inv = (me > mb) ? 1.0f / (float)(me - mb) : 0.0f;
    acc.x *= inv; acc.y *= inv; acc.z *= inv; acc.w *= inv;
    *(float4*)(g_xc + (size_t)w * HID + lane * 4) = acc;
    __nv_bfloat162 lo = __floats2bfloat162_rn(acc.x, acc.y);
    __nv_bfloat162 hi = __floats2bfloat162_rn(acc.z, acc.w);
    uint2 o;
    o.x = *(uint32_t*)&lo;
    o.y = *(uint32_t*)&hi;
    *(uint2*)&g_xcb[(size_t)w * 64 + lane * 2] = o;
}

// ---------------- fused cluster layer: SMEM-hash dedup + MLP-4 gather -----------
__global__ __launch_bounds__(256) void cluster_fused_kernel(
    const float* __restrict__ Wl, const float* __restrict__ Wr,
    const float* __restrict__ b, const int* __restrict__ ca,
    const int* __restrict__ bp, int n, int E, int Cc)
{
    __shared__ float WlS[HID * CLS];
    __shared__ float WrS[HID * CLS];
    __shared__ float bS[CLS];
    __shared__ int hsh[8][512];

    int tid = threadIdx.x;
    int lane = tid & 31, wid = tid >> 5;

    for (int i = tid; i < HID * CLS; i += blockDim.x) {
        WlS[i] = Wl[i];
        WrS[i] = Wr[i];
    }
    if (tid < CLS) bS[tid] = b[tid];
    for (int i = lane; i < 512; i += 32) hsh[wid][i] = 0;
    __syncthreads();

    int w = (int)(((unsigned)blockIdx.x * blockDim.x + tid) >> 5);
    if (w >= Cc) return;

    const uint2* xcb = (const uint2*)g_xcb;
    float4 acc = make_float4(0, 0, 0, 0);
    int nuniq = 0;
    int mb = g_off[n + w] - E, me = g_off[n + w + 1] - E;
    for (int mi = mb; mi < me; mi++) {
        int node = g_cnodes[mi];
        int eb = g_off[node], ee = g_off[node + 1];
        for (int j0 = eb; j0 < ee; j0 += 32) {
            int j = j0 + lane;
            int isnew = 0, cu = 0;
            if (j < ee) {
                int s = g_esrt[j];
                cu = __ldg(ca + s);
                int key = cu + 1;
                unsigned h = ((unsigned)cu * 2654435761u) >> 23;
                h &= 511;
                while (true) {
                    int old = atomicCAS(&hsh[wid][h], 0, key);
                    if (old == 0) { isnew = 1; break; }
                    if (old == key) break;
                    h = (h + 1) & 511;
                }
            }
            unsigned m = __ballot_sync(0xffffffffu, isnew);
            nuniq += __popc(m);
            while (m) {
                int b0 = __ffs(m) - 1;             m &= m - 1;
                int b1 = m ? __ffs(m) - 1 : 32; if (b1 < 32) m &= m - 1;
                int b2 = m ? __ffs(m) - 1 : 32; if (b2 < 32) m &= m - 1;
                int b3 = m ? __ffs(m) - 1 : 32; if (b3 < 32) m &= m - 1;
                int c0 = __shfl_sync(0xffffffffu, cu, b0);
                int c1 = __shfl_sync(0xffffffffu, cu, b1 & 31);
                int c2 = __shfl_sync(0xffffffffu, cu, b2 & 31);
                int c3 = __shfl_sync(0xffffffffu, cu, b3 & 31);
                uint2 u0 = __ldg(xcb + (size_t)c0 * 32 + lane);
                uint2 u1 = make_uint2(0, 0), u2 = make_uint2(0, 0), u3 = make_uint2(0, 0);
                if (b1 < 32) u1 = __ldg(xcb + (size_t)c1 * 32 + lane);
                if (b2 < 32) u2 = __ldg(xcb + (size_t)c2 * 32 + lane);
                if (b3 < 32) u3 = __ldg(xcb + (size_t)c3 * 32 + lane);
                bf16acc(acc, u0);
                if (b1 < 32) bf16acc(acc, u1);
                if (b2 < 32) bf16acc(acc, u2);
                if (b3 < 32) bf16acc(acc, u3);
            }
        }
    }
    float inv = nuniq > 0 ? 1.0f / (float)nuniq : 0.0f;
    float4 a = make_float4(acc.x * inv, acc.y * inv, acc.z * inv, acc.w * inv);
    float4 xv = *(const float4*)(g_xc + (size_t)w * HID + lane * 4);

    float c[CLS];
    int k0 = lane * 4;
    #pragma unroll
    for (int j = 0; j < CLS; j++) {
        float s = a.x * WlS[(k0 + 0) * CLS + j] + xv.x * WrS[(k0 + 0) * CLS + j];
        s += a.y * WlS[(k0 + 1) * CLS + j] + xv.y * WrS[(k0 + 1) * CLS + j];
        s += a.z * WlS[(k0 + 2) * CLS + j] + xv.z * WrS[(k0 + 2) * CLS + j];
        s += a.w * WlS[(k0 + 3) * CLS + j] + xv.w * WrS[(k0 + 3) * CLS + j];
        c[j] = s;
    }
    #pragma unroll
    for (int j = 0; j < CLS; j++) {
        #pragma unroll
        for (int off = 16; off; off >>= 1)
            c[j] += __shfl_xor_sync(0xffffffffu, c[j], off);
    }
    float ss = 0.0f;
    #pragma unroll
    for (int j = 0; j < CLS; j++) { c[j] += bS[j]; ss += c[j] * c[j]; }
    float rn = rsqrtf(ss);
    int g = __ldg(bp + w);
    if (lane < CLS) atomicAdd(&Zgsum[g * CLS + lane], c[lane] * rn);
    if (lane == 0) atomicAdd(&Zgcnt[g], 1);
}

__global__ void final_kernel(float* __restrict__ out, int G) {
    int g = blockIdx.x * blockDim.x + threadIdx.x;
    if (g >= G) return;
    int cnt = Zgcnt[g];
    float inv = cnt > 0 ? 1.0f / (float)cnt : 0.0f;
    float v[CLS];
    float mx = -1e30f;
    #pragma unroll
    for (int j = 0; j < CLS; j++) { v[j] = Zgsum[g * CLS + j] * inv; mx = fmaxf(mx, v[j]); }
    float s = 0.0f;
    #pragma unroll
    for (int j = 0; j < CLS; j++) s += expf(v[j] - mx);
    float lse = logf(s) + mx;
    #pragma unroll
    for (int j = 0; j < CLS; j++) out[g * CLS + j] = v[j] - lse;
}

// ---------------- launch ---------------------------------------------------------
extern "C" void kernel_launch(void* const* d_in, const int* in_sizes, int n_in,
                              void* d_out, int out_size) {
    const float* x     = (const float*)d_in[0];
    const float* Wl_in = (const float*)d_in[1];
    const float* Wr_in = (const float*)d_in[2];
    const float* b_in  = (const float*)d_in[3];
    const float* Wl_h  = (const float*)d_in[4];
    const float* Wr_h  = (const float*)d_in[5];
    const float* b_h   = (const float*)d_in[6];
    const float* Wl_o  = (const float*)d_in[7];
    const float* Wr_o  = (const float*)d_in[8];
    const float* b_o   = (const float*)d_in[9];
    const int* esrc = (const int*)d_in[10];
    const int* edst = (const int*)d_in[11];
    const int* ca   = (const int*)d_in[12];
    const int* bp   = (const int*)d_in[13];

    int n  = in_sizes[0] / HID;
    int E  = in_sizes[10];
    int Cc = in_sizes[13];
    int G  = out_size / CLS;
    int m  = n + Cc;
    float* out = (float*)d_out;

    void *p_zero, *p_off, *p_cur, *p_xb, *p_h1b, *p_h2b, *p_bfrag;
    cudaGetSymbolAddress(&p_zero,  g_zero);
    cudaGetSymbolAddress(&p_off,   g_off);
    cudaGetSymbolAddress(&p_cur,   g_cur);
    cudaGetSymbolAddress(&p_xb,    g_xb);
    cudaGetSymbolAddress(&p_h1b,   g_h1b);
    cudaGetSymbolAddress(&p_h2b,   g_h2b);
    cudaGetSymbolAddress(&p_bfrag, g_bfrag);

    cudaFuncSetAttribute(node_layer<0>,
                         cudaFuncAttributeMaxDynamicSharedMemorySize, SMEM_NODE);
    cudaFuncSetAttribute(node_layer<1>,
                         cudaFuncAttributeMaxDynamicSharedMemorySize, SMEM_NODE);

    cudaMemsetAsync(p_zero, 0, (size_t)ZTOTAL * sizeof(int));

    // prep: histograms + B frags + bf16 x
    int pthreads = 2 * 32 * 16 * 32 + n * 32;
    if (pthreads < E) pthreads = E;
    prep_count_kernel<<<(pthreads + 255) / 256, 256>>>(
        edst, ca, Wl_in, Wr_in, Wl_h, Wr_h, x, (uint2*)p_xb, E, n);

    int nb = (m + SCAN_B - 1) / SCAN_B;
    scan_lookback<<<nb, SCAN_B>>>((const int*)p_zero, (int*)p_off, (int*)p_cur, m);

    int cover = (E > n) ? E : n;
    fill_kernel<<<(cover + 255) / 256, 256>>>(esrc, edst, ca, E, n);

    const float2* bfrag = (const float2*)p_bfrag;
    int tiles = (n + 63) / 64;

    // layer 1: gather bf16 x, self fp32 x -> h1 bf16
    node_layer<0><<<tiles, 256, SMEM_NODE>>>(
        (const uint2*)p_xb, x, nullptr, bfrag, b_in, (uint32_t*)p_h1b, n);
    // layer 2: gather bf16 h1, self bf16 h1 -> h2 bf16
    node_layer<1><<<tiles, 256, SMEM_NODE>>>(
        (const uint2*)p_h1b, nullptr, (const uint2*)p_h1b,
        bfrag + 32 * 16 * 32, b_h, (uint32_t*)p_h2b, n);

    xc_kernel<<<(Cc + 7) / 8, 256>>>((const uint2*)p_h2b, n, E, Cc);
    cluster_fused_kernel<<<(Cc + 7) / 8, 256>>>(Wl_o, Wr_o, b_o, ca, bp, n, E, Cc);

    final_kernel<<<(G + 63) / 64, 64>>>(out, G);
}

// round 8
// speedup vs baseline: 1.4238x; 1.0981x over previous
#include <cuda_runtime.h>
#include <cuda_bf16.h>
#include <math.h>
#include <stdint.h>

#define HID 128
#define CLS 10
#define NMAX 100000
#define EMAX 1600000
#define CMAX 50000
#define GMAX 64
#define SCAN_B 256
#define MTOT (NMAX + CMAX)
#define NTILES 1024

typedef unsigned long long ull;

// ---------------- scratch (device globals) -----------------------------------
__device__ __align__(256) float g_xc[(size_t)CMAX * HID];   // fp32 cluster means
__device__ __align__(16) uint32_t g_xb  [(size_t)NMAX * 64]; // bf16 x
__device__ __align__(16) uint32_t g_h1b [(size_t)NMAX * 64]; // bf16 h1
__device__ __align__(16) uint32_t g_h2b [(size_t)NMAX * 64]; // bf16 h2
__device__ __align__(16) uint32_t g_aggb[(size_t)NMAX * 64]; // bf16 neighbor-mean
__device__ __align__(16) uint32_t g_xcb [(size_t)CMAX * 64]; // bf16 xc
__device__ __align__(16) float2 g_bfrag[2 * 32 * 16 * 32];   // tf32 B frags
__device__ int g_off[MTOT + 1];
__device__ int g_cur[MTOT];
__device__ int g_esrt[EMAX];
__device__ int g_cnodes[NMAX];

// single zeroed region
__device__ int g_zero[MTOT + NTILES + GMAX * CLS + GMAX];
#define Zcnt   (g_zero)
#define Ztst   ((unsigned*)(g_zero + MTOT))
#define Zgsum  ((float*)(g_zero + MTOT + NTILES))
#define Zgcnt  (g_zero + MTOT + NTILES + GMAX * CLS)
#define ZTOTAL (MTOT + NTILES + GMAX * CLS + GMAX)

// ---------------- helpers ------------------------------------------------------
__device__ __forceinline__ float tf32r(float f) {
    uint32_t o;
    asm("cvt.rna.tf32.f32 %0, %1;" : "=r"(o) : "f"(f));
    return __uint_as_float(o);
}
__device__ __forceinline__ void mma8(float d[4], const unsigned a[4],
                                     unsigned b0, unsigned b1) {
    asm volatile("mma.sync.aligned.m16n8k8.row.col.f32.tf32.tf32.f32 "
                 "{%0,%1,%2,%3}, {%4,%5,%6,%7}, {%8,%9}, {%0,%1,%2,%3};"
                 : "+f"(d[0]), "+f"(d[1]), "+f"(d[2]), "+f"(d[3])
                 : "r"(a[0]), "r"(a[1]), "r"(a[2]), "r"(a[3]), "r"(b0), "r"(b1));
}
__device__ __forceinline__ void bf16acc(float4& acc, uint2 u) {
    float2 p = __bfloat1622float2(*(__nv_bfloat162*)&u.x);
    float2 q = __bfloat1622float2(*(__nv_bfloat162*)&u.y);
    acc.x += p.x; acc.y += p.y; acc.z += q.x; acc.w += q.y;
}
__device__ __forceinline__ uint2 packbf(float4 v) {
    __nv_bfloat162 lo = __floats2bfloat162_rn(v.x, v.y);
    __nv_bfloat162 hi = __floats2bfloat162_rn(v.z, v.w);
    uint2 o;
    o.x = *(uint32_t*)&lo;
    o.y = *(uint32_t*)&hi;
    return o;
}
__device__ __forceinline__ void st_rel(unsigned* p, unsigned v) {
    asm volatile("st.release.gpu.u32 [%0], %1;" :: "l"(p), "r"(v) : "memory");
}
__device__ __forceinline__ unsigned ld_acq(unsigned* p) {
    unsigned v;
    asm volatile("ld.acquire.gpu.u32 %0, [%1];" : "=r"(v) : "l"(p) : "memory");
    return v;
}

// frag layout: 32 ksteps x 4 mtiles x 32 lanes x 4 comps, ks-stride padded (+4)
#define AFRAG(ks, mt, ln) ((ks) * 516 + ((mt) * 32 + (ln)) * 4)
__device__ __forceinline__ int fragidx(int r, int c) {
    return AFRAG(c >> 3, r >> 4, ((r & 7) << 2) | (c & 3))
         + 2 * ((c >> 2) & 1) + ((r >> 3) & 1);
}
#define SMEM_NODE ((32 * 516 + 64) * 4)

// ---------------- prep: histograms + B frags + bf16 x ---------------------------
__global__ void prep_count_kernel(const int* __restrict__ dst, const int* __restrict__ ca,
                                  const float* __restrict__ Wl0, const float* __restrict__ Wr0,
                                  const float* __restrict__ Wl1, const float* __restrict__ Wr1,
                                  const float* __restrict__ x, uint2* __restrict__ xb,
                                  int E, int n) {
    int i = blockIdx.x * blockDim.x + threadIdx.x;
    if (i < E) atomicAdd(&Zcnt[dst[i]], 1);
    if (i < n) atomicAdd(&Zcnt[n + ca[i]], 1);
    if (i < 2 * 32 * 16 * 32) {
        int lane = i & 31, nt = (i >> 5) & 15, ks = (i >> 9) & 31, layer = i >> 14;
        const float* W = layer ? (ks < 16 ? Wl1 : Wr1) : (ks < 16 ? Wl0 : Wr0);
        int kl = ks & 15;
        int k0 = kl * 8 + (lane & 3);
        int nn = nt * 8 + (lane >> 2);
        float2 o;
        o.x = tf32r(W[(size_t)k0 * HID + nn]);
        o.y = tf32r(W[(size_t)(k0 + 4) * HID + nn]);
        g_bfrag[i] = o;
    }
    int j = i - 2 * 32 * 16 * 32;
    if (j >= 0 && j < n * 32) {
        float4 v = *(const float4*)(x + (size_t)j * 4);
        xb[j] = packbf(v);
    }
}

// ---------------- single-pass decoupled-lookback exclusive scan -----------------
__global__ void scan_lookback(const int* __restrict__ in, int* __restrict__ off,
                              int* __restrict__ cur, int m) {
    __shared__ int sh[SCAN_B];
    __shared__ int s_prev;
    int b = blockIdx.x;
    int i = b * SCAN_B + threadIdx.x;
    int v = (i < m) ? in[i] : 0;
    sh[threadIdx.x] = v;
    __syncthreads();
    #pragma unroll
    for (int o = 1; o < SCAN_B; o <<= 1) {
        int t = (threadIdx.x >= o) ? sh[threadIdx.x - o] : 0;
        __syncthreads();
        sh[threadIdx.x] += t;
        __syncthreads();
    }
    int agg = sh[SCAN_B - 1];
    if (threadIdx.x == 0) {
        if (b == 0) {
            st_rel(&Ztst[0], (2u << 30) | (unsigned)agg);
            s_prev = 0;
        } else {
            st_rel(&Ztst[b], (1u << 30) | (unsigned)agg);
            int prev = 0, j = b - 1;
            while (true) {
                unsigned s;
                do { s = ld_acq(&Ztst[j]); } while ((s >> 30) == 0);
                prev += (int)(s & 0x3FFFFFFFu);
                if ((s >> 30) == 2u) break;
                j--;
            }
            st_rel(&Ztst[b], (2u << 30) | (unsigned)(prev + agg));
            s_prev = prev;
        }
    }
    __syncthreads();
    int excl = s_prev + sh[threadIdx.x] - v;
    if (i < m) {
        off[i] = excl;
        cur[i] = excl;
        if (i == m - 1) off[m] = excl + v;
    }
}

// ---------------- fill both CSR payloads ----------------------------------------
__global__ void fill_kernel(const int* __restrict__ src, const int* __restrict__ dst,
                            const int* __restrict__ ca, int E, int n) {
    int i = blockIdx.x * blockDim.x + threadIdx.x;
    if (i < E) {
        int d = dst[i];
        int pos = atomicAdd(&g_cur[d], 1);
        g_esrt[pos] = src[i];
    }
    if (i < n) {
        int c = ca[i];
        int pos = atomicAdd(&g_cur[n + c], 1);
        g_cnodes[pos - E] = i;
    }
}

// ---------------- gather: warp per node, MLP-8, bf16 in/out ---------------------
__global__ __launch_bounds__(512) void gather_kernel(const uint2* __restrict__ tab,
                                                     uint2* __restrict__ aggb, int n) {
    int w = (int)(((unsigned)blockIdx.x * blockDim.x + threadIdx.x) >> 5);
    if (w >= n) return;
    int lane = threadIdx.x & 31;
    int off = g_off[w], end = g_off[w + 1];
    float4 acc = make_float4(0, 0, 0, 0);
    int j = off;
    for (; j + 8 <= end; j += 8) {
        int s[8];
        uint2 u[8];
        #pragma unroll
        for (int q = 0; q < 8; q++) s[q] = __ldg(g_esrt + j + q);
        #pragma unroll
        for (int q = 0; q < 8; q++) u[q] = __ldg(tab + (size_t)s[q] * 32 + lane);
        #pragma unroll
        for (int q = 0; q < 8; q++) bf16acc(acc, u[q]);
    }
    for (; j + 2 <= end; j += 2) {
        int s0 = __ldg(g_esrt + j), s1 = __ldg(g_esrt + j + 1);
        uint2 u0 = __ldg(tab + (size_t)s0 * 32 + lane);
        uint2 u1 = __ldg(tab + (size_t)s1 * 32 + lane);
        bf16acc(acc, u0);
        bf16acc(acc, u1);
    }
    if (j < end) {
        int s = __ldg(g_esrt + j);
        bf16acc(acc, __ldg(tab + (size_t)s * 32 + lane));
    }
    float inv = (end > off) ? 1.0f / (float)(end - off) : 0.0f;
    acc.x *= inv; acc.y *= inv; acc.z *= inv; acc.w *= inv;
    aggb[(size_t)w * 32 + lane] = packbf(acc);
}

// ---------------- GEMM layer: coalesced bf16 A-halves -> tf32 MMA -> norm -------
__global__ __launch_bounds__(256, 3) void gemm_layer(
    const uint2* __restrict__ aggb, const uint2* __restrict__ selfb,
    const float2* __restrict__ bfrag, const float* __restrict__ bias,
    uint32_t* __restrict__ houtb, int n)
{
    extern __shared__ float sm[];
    float* rowss = sm + 32 * 516;
    int tid = threadIdx.x, lane = tid & 31, wid = tid >> 5;
    int n0 = blockIdx.x * 64;
    if (tid < 64) rowss[tid] = 0.0f;

    // ---- load both A-halves into frags (warp per row, coalesced) ----
    #pragma unroll
    for (int part = 0; part < 2; part++) {
        const uint2* tab = part ? selfb : aggb;
        for (int r = wid; r < 64; r += 8) {
            int node = n0 + r;
            float4 v = make_float4(0, 0, 0, 0);
            if (node < n) {
                uint2 u = __ldg(tab + (size_t)node * 32 + lane);
                float2 p = __bfloat1622float2(*(__nv_bfloat162*)&u.x);
                float2 q = __bfloat1622float2(*(__nv_bfloat162*)&u.y);
                v = make_float4(p.x, p.y, q.x, q.y);
            }
            int base = AFRAG(part * 16 + (lane >> 1), r >> 4, (r & 7) << 2);
            int comp = 2 * (lane & 1) + ((r >> 3) & 1);
            sm[base + 0 + comp]  = tf32r(v.x);
            sm[base + 4 + comp]  = tf32r(v.y);
            sm[base + 8 + comp]  = tf32r(v.z);
            sm[base + 12 + comp] = tf32r(v.w);
        }
    }
    __syncthreads();

    // ---- MMA: 32 ksteps ----
    int warp_m = wid >> 2, warp_n = wid & 3;
    float d[2][4][4] = {};
    #pragma unroll 4
    for (int ks = 0; ks < 32; ks++) {
        unsigned a[2][4];
        #pragma unroll
        for (int t = 0; t < 2; t++) {
            float4 v = *(float4*)&sm[AFRAG(ks, warp_m * 2 + t, lane)];
            a[t][0] = __float_as_uint(v.x); a[t][1] = __float_as_uint(v.y);
            a[t][2] = __float_as_uint(v.z); a[t][3] = __float_as_uint(v.w);
        }
        #pragma unroll
        for (int u = 0; u < 4; u++) {
            float2 bv = __ldg(&bfrag[(size_t)(ks * 16 + warp_n * 4 + u) * 32 + lane]);
            unsigned b0 = __float_as_uint(bv.x), b1 = __float_as_uint(bv.y);
            mma8(d[0][u], a[0], b0, b1);
            mma8(d[1][u], a[1], b0, b1);
        }
    }

    // ---- epilogue: bias + relu + cross-warp row norm ----
    float2 bb[4];
    #pragma unroll
    for (int u = 0; u < 4; u++)
        bb[u] = *(const float2*)(bias + warp_n * 32 + u * 8 + (lane & 3) * 2);

    #pragma unroll
    for (int t = 0; t < 2; t++) {
        float ss0 = 0, ss1 = 0;
        #pragma unroll
        for (int u = 0; u < 4; u++) {
            float c0 = fmaxf(d[t][u][0] + bb[u].x, 0.0f);
            float c1 = fmaxf(d[t][u][1] + bb[u].y, 0.0f);
            float c2 = fmaxf(d[t][u][2] + bb[u].x, 0.0f);
            float c3 = fmaxf(d[t][u][3] + bb[u].y, 0.0f);
            ss0 += c0 * c0 + c1 * c1;
            ss1 += c2 * c2 + c3 * c3;
            d[t][u][0] = c0; d[t][u][1] = c1; d[t][u][2] = c2; d[t][u][3] = c3;
        }
        int lr = (warp_m * 2 + t) * 16 + (lane >> 2);
        atomicAdd(&rowss[lr], ss0);
        atomicAdd(&rowss[lr + 8], ss1);
    }
    __syncthreads();

    #pragma unroll
    for (int t = 0; t < 2; t++) {
        int r1 = (warp_m * 2 + t) * 16 + (lane >> 2);
        float rn0 = rsqrtf(rowss[r1]);
        float rn1 = rsqrtf(rowss[r1 + 8]);
        #pragma unroll
        for (int u = 0; u < 4; u++) {
            int c1 = warp_n * 32 + u * 8 + (lane & 3) * 2;
            sm[fragidx(r1, c1)]         = d[t][u][0] * rn0;
            sm[fragidx(r1, c1 + 1)]     = d[t][u][1] * rn0;
            sm[fragidx(r1 + 8, c1)]     = d[t][u][2] * rn1;
            sm[fragidx(r1 + 8, c1 + 1)] = d[t][u][3] * rn1;
        }
    }
    __syncthreads();

    #pragma unroll
    for (int e = 0; e < 16; e++) {
        int p = tid + e * 256;
        int r = p >> 6, cp = p & 63;
        int node = n0 + r;
        if (node >= n) continue;
        int c = cp * 2;
        float v0 = sm[fragidx(r, c)];
        float v1 = sm[fragidx(r, c + 1)];
        __nv_bfloat162 bh = __floats2bfloat162_rn(v0, v1);
        houtb[(size_t)node * 64 + cp] = *(uint32_t*)&bh;
    }
}

// ---------------- cluster mean from bf16 h2: warp per cluster -------------------
__global__ void xc_kernel(const uint2* __restrict__ h2b, int n, int E, int Cc) {
    int w = (int)(((unsigned)blockIdx.x * blockDim.x + threadIdx.x) >> 5);
    if (w >= Cc) return;
    int lane = threadIdx.x & 31;
    int mb = g_off[n + w] - E, me = g_off[n + w + 1] - E;
    float4 acc = make_float4(0, 0, 0, 0);
    int mi = mb;
    for (; mi + 2 <= me; mi += 2) {
        int n0 = g_cnodes[mi], n1 = g_cnodes[mi + 1];
        uint2 u0 = __ldg(h2b + (size_t)n0 * 32 + lane);
        uint2 u1 = __ldg(h2b + (size_t)n1 * 32 + lane);
        bf16acc(acc, u0);
        bf16acc(acc, u1);
    }
    if (mi < me) {
        int n0 = g_cnodes[mi];
        bf16acc(acc, __ldg(h2b + (size_t)n0 * 32 + lane));
    }
    float inv = (me > mb) ? 1.0f / (float)(me - mb) : 0.0f;
    acc.x *= inv; acc.y *= inv; acc.z *= inv; acc.w *= inv;
    *(float4*)(g_xc + (size_t)w * HID + lane * 4) = acc;
    *(uint2*)&g_xcb[(size_t)w * 64 + lane * 2] = packbf(acc);
}

// ---------------- fused cluster layer: SMEM-hash dedup + MLP-4 gather -----------
__global__ __launch_bounds__(256) void cluster_fused_kernel(
    const float* __restrict__ Wl, const float* __restrict__ Wr,
    const float* __restrict__ b, const int* __restrict__ ca,
    const int* __restrict__ bp, int n, int E, int Cc)
{
    __shared__ float WlS[HID * CLS];
    __shared__ float WrS[HID * CLS];
    __shared__ float bS[CLS];
    __shared__ int hsh[8][512];

    int tid = threadIdx.x;
    int lane = tid & 31, wid = tid >> 5;

    for (int i = tid; i < HID * CLS; i += blockDim.x) {
        WlS[i] = Wl[i];
        WrS[i] = Wr[i];
    }
    if (tid < CLS) bS[tid] = b[tid];
    for (int i = lane; i < 512; i += 32) hsh[wid][i] = 0;
    __syncthreads();

    int w = (int)(((unsigned)blockIdx.x * blockDim.x + tid) >> 5);
    if (w >= Cc) return;

    const uint2* xcb = (const uint2*)g_xcb;
    float4 acc = make_float4(0, 0, 0, 0);
    int nuniq = 0;
    int mb = g_off[n + w] - E, me = g_off[n + w + 1] - E;
    for (int mi = mb; mi < me; mi++) {
        int node = g_cnodes[mi];
        int eb = g_off[node], ee = g_off[node + 1];
        for (int j0 = eb; j0 < ee; j0 += 32) {
            int j = j0 + lane;
            int isnew = 0, cu = 0;
            if (j < ee) {
                int s = g_esrt[j];
                cu = __ldg(ca + s);
                int key = cu + 1;
                unsigned h = ((unsigned)cu * 2654435761u) >> 23;
                h &= 511;
                while (true) {
                    int old = atomicCAS(&hsh[wid][h], 0, key);
                    if (old == 0) { isnew = 1; break; }
                    if (old == key) break;
                    h = (h + 1) & 511;
                }
            }
            unsigned m = __ballot_sync(0xffffffffu, isnew);
            nuniq += __popc(m);
            while (m) {
                int b0 = __ffs(m) - 1;             m &= m - 1;
                int b1 = m ? __ffs(m) - 1 : 32; if (b1 < 32) m &= m - 1;
                int b2 = m ? __ffs(m) - 1 : 32; if (b2 < 32) m &= m - 1;
                int b3 = m ? __ffs(m) - 1 : 32; if (b3 < 32) m &= m - 1;
                int c0 = __shfl_sync(0xffffffffu, cu, b0);
                int c1 = __shfl_sync(0xffffffffu, cu, b1 & 31);
                int c2 = __shfl_sync(0xffffffffu, cu, b2 & 31);
                int c3 = __shfl_sync(0xffffffffu, cu, b3 & 31);
                uint2 u0 = __ldg(xcb + (size_t)c0 * 32 + lane);
                uint2 u1 = make_uint2(0, 0), u2 = make_uint2(0, 0), u3 = make_uint2(0, 0);
                if (b1 < 32) u1 = __ldg(xcb + (size_t)c1 * 32 + lane);
                if (b2 < 32) u2 = __ldg(xcb + (size_t)c2 * 32 + lane);
                if (b3 < 32) u3 = __ldg(xcb + (size_t)c3 * 32 + lane);
                bf16acc(acc, u0);
                if (b1 < 32) bf16acc(acc, u1);
                if (b2 < 32) bf16acc(acc, u2);
                if (b3 < 32) bf16acc(acc, u3);
            }
        }
    }
    float inv = nuniq > 0 ? 1.0f / (float)nuniq : 0.0f;
    float4 a = make_float4(acc.x * inv, acc.y * inv, acc.z * inv, acc.w * inv);
    float4 xv = *(const float4*)(g_xc + (size_t)w * HID + lane * 4);

    float c[CLS];
    int k0 = lane * 4;
    #pragma unroll
    for (int j = 0; j < CLS; j++) {
        float s = a.x * WlS[(k0 + 0) * CLS + j] + xv.x * WrS[(k0 + 0) * CLS + j];
        s += a.y * WlS[(k0 + 1) * CLS + j] + xv.y * WrS[(k0 + 1) * CLS + j];
        s += a.z * WlS[(k0 + 2) * CLS + j] + xv.z * WrS[(k0 + 2) * CLS + j];
        s += a.w * WlS[(k0 + 3) * CLS + j] + xv.w * WrS[(k0 + 3) * CLS + j];
        c[j] = s;
    }
    #pragma unroll
    for (int j = 0; j < CLS; j++) {
        #pragma unroll
        for (int off = 16; off; off >>= 1)
            c[j] += __shfl_xor_sync(0xffffffffu, c[j], off);
    }
    float ss = 0.0f;
    #pragma unroll
    for (int j = 0; j < CLS; j++) { c[j] += bS[j]; ss += c[j] * c[j]; }
    float rn = rsqrtf(ss);
    int g = __ldg(bp + w);
    if (lane < CLS) atomicAdd(&Zgsum[g * CLS + lane], c[lane] * rn);
    if (lane == 0) atomicAdd(&Zgcnt[g], 1);
}

__global__ void final_kernel(float* __restrict__ out, int G) {
    int g = blockIdx.x * blockDim.x + threadIdx.x;
    if (g >= G) return;
    int cnt = Zgcnt[g];
    float inv = cnt > 0 ? 1.0f / (float)cnt : 0.0f;
    float v[CLS];
    float mx = -1e30f;
    #pragma unroll
    for (int j = 0; j < CLS; j++) { v[j] = Zgsum[g * CLS + j] * inv; mx = fmaxf(mx, v[j]); }
    float s = 0.0f;
    #pragma unroll
    for (int j = 0; j < CLS; j++) s += expf(v[j] - mx);
    float lse = logf(s) + mx;
    #pragma unroll
    for (int j = 0; j < CLS; j++) out[g * CLS + j] = v[j] - lse;
}

// ---------------- launch ---------------------------------------------------------
extern "C" void kernel_launch(void* const* d_in, const int* in_sizes, int n_in,
                              void* d_out, int out_size) {
    const float* x     = (const float*)d_in[0];
    const float* Wl_in = (const float*)d_in[1];
    const float* Wr_in = (const float*)d_in[2];
    const float* b_in  = (const float*)d_in[3];
    const float* Wl_h  = (const float*)d_in[4];
    const float* Wr_h  = (const float*)d_in[5];
    const float* b_h   = (const float*)d_in[6];
    const float* Wl_o  = (const float*)d_in[7];
    const float* Wr_o  = (const float*)d_in[8];
    const float* b_o   = (const float*)d_in[9];
    const int* esrc = (const int*)d_in[10];
    const int* edst = (const int*)d_in[11];
    const int* ca   = (const int*)d_in[12];
    const int* bp   = (const int*)d_in[13];

    int n  = in_sizes[0] / HID;
    int E  = in_sizes[10];
    int Cc = in_sizes[13];
    int G  = out_size / CLS;
    int m  = n + Cc;
    float* out = (float*)d_out;

    void *p_zero, *p_off, *p_cur, *p_xb, *p_h1b, *p_h2b, *p_aggb, *p_bfrag;
    cudaGetSymbolAddress(&p_zero,  g_zero);
    cudaGetSymbolAddress(&p_off,   g_off);
    cudaGetSymbolAddress(&p_cur,   g_cur);
    cudaGetSymbolAddress(&p_xb,    g_xb);
    cudaGetSymbolAddress(&p_h1b,   g_h1b);
    cudaGetSymbolAddress(&p_h2b,   g_h2b);
    cudaGetSymbolAddress(&p_aggb,  g_aggb);
    cudaGetSymbolAddress(&p_bfrag, g_bfrag);

    cudaFuncSetAttribute(gemm_layer,
                         cudaFuncAttributeMaxDynamicSharedMemorySize, SMEM_NODE);

    cudaMemsetAsync(p_zero, 0, (size_t)ZTOTAL * sizeof(int));

    int pthreads = 2 * 32 * 16 * 32 + n * 32;
    if (pthreads < E) pthreads = E;
    prep_count_kernel<<<(pthreads + 255) / 256, 256>>>(
        edst, ca, Wl_in, Wr_in, Wl_h, Wr_h, x, (uint2*)p_xb, E, n);

    int nb = (m + SCAN_B - 1) / SCAN_B;
    scan_lookback<<<nb, SCAN_B>>>((const int*)p_zero, (int*)p_off, (int*)p_cur, m);

    int cover = (E > n) ? E : n;
    fill_kernel<<<(cover + 255) / 256, 256>>>(esrc, edst, ca, E, n);

    const float2* bfrag = (const float2*)p_bfrag;
    int tiles = (n + 63) / 64;
    int gwb = (n + 15) / 16;   // warp per node, 512 threads = 16 warps/block

    // layer 1
    gather_kernel<<<gwb, 512>>>((const uint2*)p_xb, (uint2*)p_aggb, n);
    gemm_layer<<<tiles, 256, SMEM_NODE>>>(
        (const uint2*)p_aggb, (const uint2*)p_xb, bfrag, b_in, (uint32_t*)p_h1b, n);
    // layer 2
    gather_kernel<<<gwb, 512>>>((const uint2*)p_h1b, (uint2*)p_aggb, n);
    gemm_layer<<<tiles, 256, SMEM_NODE>>>(
        (const uint2*)p_aggb, (const uint2*)p_h1b, bfrag + 32 * 16 * 32, b_h,
        (uint32_t*)p_h2b, n);

    xc_kernel<<<(Cc + 7) / 8, 256>>>((const uint2*)p_h2b, n, E, Cc);
    cluster_fused_kernel<<<(Cc + 7) / 8, 256>>>(Wl_o, Wr_o, b_o, ca, bp, n, E, Cc);

    final_kernel<<<(G + 63) / 64, 64>>>(out, G);
}

// round 9
// speedup vs baseline: 1.6025x; 1.1255x over previous
#include <cuda_runtime.h>
#include <cuda_bf16.h>
#include <math.h>
#include <stdint.h>

#define HID 128
#define CLS 10
#define NMAX 100000
#define EMAX 1600000
#define CMAX 50000
#define GMAX 64
#define SCAN_B 256
#define MTOT (NMAX + CMAX)
#define NTILES 1024

typedef unsigned long long ull;

// ---------------- scratch (device globals) -----------------------------------
__device__ __align__(256) float g_xc[(size_t)CMAX * HID];   // fp32 cluster means
__device__ __align__(16) uint32_t g_xb  [(size_t)NMAX * 64]; // bf16 x
__device__ __align__(16) uint32_t g_h1b [(size_t)NMAX * 64]; // bf16 h1
__device__ __align__(16) uint32_t g_h2b [(size_t)NMAX * 64]; // bf16 h2
__device__ __align__(16) uint32_t g_aggb[(size_t)NMAX * 64]; // bf16 neighbor-mean
__device__ __align__(16) uint32_t g_xcb [(size_t)CMAX * 64]; // bf16 xc
__device__ __align__(16) uint2 g_bfrag[2 * 16 * 16 * 32];    // bf16 B frags (2 layers x 16 ks16)
__device__ int g_off[MTOT + 1];
__device__ int g_cur[MTOT];
__device__ int g_esrt[EMAX];
__device__ int g_cnodes[NMAX];

// single zeroed region
__device__ int g_zero[MTOT + NTILES + GMAX * CLS + GMAX];
#define Zcnt   (g_zero)
#define Ztst   ((unsigned*)(g_zero + MTOT))
#define Zgsum  ((float*)(g_zero + MTOT + NTILES))
#define Zgcnt  (g_zero + MTOT + NTILES + GMAX * CLS)
#define ZTOTAL (MTOT + NTILES + GMAX * CLS + GMAX)

// ---------------- helpers ------------------------------------------------------
__device__ __forceinline__ void mma_bf16(float d[4], const uint32_t a[4],
                                         uint32_t b0, uint32_t b1) {
    asm volatile("mma.sync.aligned.m16n8k16.row.col.f32.bf16.bf16.f32 "
                 "{%0,%1,%2,%3}, {%4,%5,%6,%7}, {%8,%9}, {%0,%1,%2,%3};"
                 : "+f"(d[0]), "+f"(d[1]), "+f"(d[2]), "+f"(d[3])
                 : "r"(a[0]), "r"(a[1]), "r"(a[2]), "r"(a[3]), "r"(b0), "r"(b1));
}
__device__ __forceinline__ void ldsm4(uint32_t r[4], uint32_t saddr) {
    asm volatile("ldmatrix.sync.aligned.m8n8.x4.shared.b16 {%0,%1,%2,%3}, [%4];"
                 : "=r"(r[0]), "=r"(r[1]), "=r"(r[2]), "=r"(r[3]) : "r"(saddr));
}
__device__ __forceinline__ void bf16acc(float4& acc, uint2 u) {
    float2 p = __bfloat1622float2(*(__nv_bfloat162*)&u.x);
    float2 q = __bfloat1622float2(*(__nv_bfloat162*)&u.y);
    acc.x += p.x; acc.y += p.y; acc.z += q.x; acc.w += q.y;
}
__device__ __forceinline__ uint2 packbf(float4 v) {
    __nv_bfloat162 lo = __floats2bfloat162_rn(v.x, v.y);
    __nv_bfloat162 hi = __floats2bfloat162_rn(v.z, v.w);
    uint2 o;
    o.x = *(uint32_t*)&lo;
    o.y = *(uint32_t*)&hi;
    return o;
}
__device__ __forceinline__ uint32_t packbf2(float a, float b) {
    __nv_bfloat162 h = __floats2bfloat162_rn(a, b);
    return *(uint32_t*)&h;
}
__device__ __forceinline__ void st_rel(unsigned* p, unsigned v) {
    asm volatile("st.release.gpu.u32 [%0], %1;" :: "l"(p), "r"(v) : "memory");
}
__device__ __forceinline__ unsigned ld_acq(unsigned* p) {
    unsigned v;
    asm volatile("ld.acquire.gpu.u32 %0, [%1];" : "=r"(v) : "l"(p) : "memory");
    return v;
}

// ---------------- prep: histograms + bf16 B frags + bf16 x ----------------------
#define NBFRAG (2 * 16 * 16 * 32)
__global__ void prep_count_kernel(const int* __restrict__ dst, const int* __restrict__ ca,
                                  const float* __restrict__ Wl0, const float* __restrict__ Wr0,
                                  const float* __restrict__ Wl1, const float* __restrict__ Wr1,
                                  const float* __restrict__ x, uint2* __restrict__ xb,
                                  int E, int n) {
    int i = blockIdx.x * blockDim.x + threadIdx.x;
    if (i < E) atomicAdd(&Zcnt[dst[i]], 1);
    if (i < n) atomicAdd(&Zcnt[n + ca[i]], 1);
    if (i < NBFRAG) {
        int lane = i & 31, nt = (i >> 5) & 15, ks = (i >> 9) & 15, layer = i >> 13;
        const float* W = layer ? (ks < 8 ? Wl1 : Wr1) : (ks < 8 ? Wl0 : Wr0);
        int k0 = (ks & 7) * 16 + 2 * (lane & 3);
        int nn = nt * 8 + (lane >> 2);
        uint2 o;
        o.x = packbf2(W[(size_t)k0 * HID + nn],       W[(size_t)(k0 + 1) * HID + nn]);
        o.y = packbf2(W[(size_t)(k0 + 8) * HID + nn], W[(size_t)(k0 + 9) * HID + nn]);
        g_bfrag[i] = o;
    }
    int j = i - NBFRAG;
    if (j >= 0 && j < n * 32) {
        float4 v = *(const float4*)(x + (size_t)j * 4);
        xb[j] = packbf(v);
    }
}

// ---------------- single-pass decoupled-lookback exclusive scan -----------------
__global__ void scan_lookback(const int* __restrict__ in, int* __restrict__ off,
                              int* __restrict__ cur, int m) {
    __shared__ int sh[SCAN_B];
    __shared__ int s_prev;
    int b = blockIdx.x;
    int i = b * SCAN_B + threadIdx.x;
    int v = (i < m) ? in[i] : 0;
    sh[threadIdx.x] = v;
    __syncthreads();
    #pragma unroll
    for (int o = 1; o < SCAN_B; o <<= 1) {
        int t = (threadIdx.x >= o) ? sh[threadIdx.x - o] : 0;
        __syncthreads();
        sh[threadIdx.x] += t;
        __syncthreads();
    }
    int agg = sh[SCAN_B - 1];
    if (threadIdx.x == 0) {
        if (b == 0) {
            st_rel(&Ztst[0], (2u << 30) | (unsigned)agg);
            s_prev = 0;
        } else {
            st_rel(&Ztst[b], (1u << 30) | (unsigned)agg);
            int prev = 0, j = b - 1;
            while (true) {
                unsigned s;
                do { s = ld_acq(&Ztst[j]); } while ((s >> 30) == 0);
                prev += (int)(s & 0x3FFFFFFFu);
                if ((s >> 30) == 2u) break;
                j--;
            }
            st_rel(&Ztst[b], (2u << 30) | (unsigned)(prev + agg));
            s_prev = prev;
        }
    }
    __syncthreads();
    int excl = s_prev + sh[threadIdx.x] - v;
    if (i < m) {
        off[i] = excl;
        cur[i] = excl;
        if (i == m - 1) off[m] = excl + v;
    }
}

// ---------------- fill both CSR payloads (2 edges/thread, MLP-2) ----------------
__global__ void fill_kernel(const int* __restrict__ src, const int* __restrict__ dst,
                            const int* __restrict__ ca, int E, int half, int n) {
    int i = blockIdx.x * blockDim.x + threadIdx.x;
    if (i < half) {
        int d0 = dst[i];
        int i1 = i + half;
        int d1 = (i1 < E) ? dst[i1] : -1;
        int p0 = atomicAdd(&g_cur[d0], 1);
        int p1 = (d1 >= 0) ? atomicAdd(&g_cur[d1], 1) : 0;
        g_esrt[p0] = src[i];
        if (d1 >= 0) g_esrt[p1] = src[i1];
    }
    if (i < n) {
        int c = ca[i];
        int pos = atomicAdd(&g_cur[n + c], 1);
        g_cnodes[pos - E] = i;
    }
}

// ---------------- gather: warp per node, MLP-8, bf16 in/out ---------------------
__global__ __launch_bounds__(512) void gather_kernel(const uint2* __restrict__ tab,
                                                     uint2* __restrict__ aggb, int n) {
    int w = (int)(((unsigned)blockIdx.x * blockDim.x + threadIdx.x) >> 5);
    if (w >= n) return;
    int lane = threadIdx.x & 31;
    int off = g_off[w], end = g_off[w + 1];
    float4 acc = make_float4(0, 0, 0, 0);
    int j = off;
    for (; j + 8 <= end; j += 8) {
        int s[8];
        uint2 u[8];
        #pragma unroll
        for (int q = 0; q < 8; q++) s[q] = __ldg(g_esrt + j + q);
        #pragma unroll
        for (int q = 0; q < 8; q++) u[q] = __ldg(tab + (size_t)s[q] * 32 + lane);
        #pragma unroll
        for (int q = 0; q < 8; q++) bf16acc(acc, u[q]);
    }
    for (; j + 2 <= end; j += 2) {
        int s0 = __ldg(g_esrt + j), s1 = __ldg(g_esrt + j + 1);
        uint2 u0 = __ldg(tab + (size_t)s0 * 32 + lane);
        uint2 u1 = __ldg(tab + (size_t)s1 * 32 + lane);
        bf16acc(acc, u0);
        bf16acc(acc, u1);
    }
    if (j < end) {
        int s = __ldg(g_esrt + j);
        bf16acc(acc, __ldg(tab + (size_t)s * 32 + lane));
    }
    float inv = (end > off) ? 1.0f / (float)(end - off) : 0.0f;
    acc.x *= inv; acc.y *= inv; acc.z *= inv; acc.w *= inv;
    aggb[(size_t)w * 32 + lane] = packbf(acc);
}

// ---------------- GEMM layer: bf16 HMMA + ldmatrix ------------------------------
// A tile: 64 rows x 256 bf16 row-major in smem (pitch 264 bf16 = 132 u32).
// ks 0..7 = agg half (Wl), ks 8..15 = self half (Wr).
#define PITCH32 132
__global__ __launch_bounds__(256, 4) void gemm_layer(
    const uint2* __restrict__ aggb, const uint2* __restrict__ selfb,
    const uint2* __restrict__ bfrag, const float* __restrict__ bias,
    uint32_t* __restrict__ houtb, int n)
{
    __shared__ uint32_t smA[64 * PITCH32];
    __shared__ float rowss[64];
    int tid = threadIdx.x, lane = tid & 31, wid = tid >> 5;
    int n0 = blockIdx.x * 64;
    if (tid < 64) rowss[tid] = 0.0f;

    // ---- load both A-halves (warp per row, coalesced uint2 stores) ----
    #pragma unroll
    for (int part = 0; part < 2; part++) {
        const uint2* tab = part ? selfb : aggb;
        for (int r = wid; r < 64; r += 8) {
            int node = n0 + r;
            uint2 u = make_uint2(0, 0);
            if (node < n) u = __ldg(tab + (size_t)node * 32 + lane);
            *(uint2*)&smA[r * PITCH32 + part * 64 + lane * 2] = u;
        }
    }
    __syncthreads();

    // ---- MMA: 16 ksteps of k16 ----
    int warp_m = wid >> 2, warp_n = wid & 3;   // warp_m 0..1 (32 rows), warp_n 0..3
    uint32_t sbase = (uint32_t)__cvta_generic_to_shared(smA);
    // ldmatrix row within 16-row tile + k-half select
    int lrow = lane & 15, khalf = (lane >> 4);   // khalf in {0,1} -> +8 bf16 = +4 u32
    float d[2][4][4] = {};
    #pragma unroll 4
    for (int ks = 0; ks < 16; ks++) {
        uint32_t a[2][4];
        #pragma unroll
        for (int t = 0; t < 2; t++) {
            int row = warp_m * 32 + t * 16 + lrow;
            uint32_t saddr = sbase + (uint32_t)(row * PITCH32 + ks * 8 + khalf * 4) * 4;
            ldsm4(a[t], saddr);
        }
        #pragma unroll
        for (int u = 0; u < 4; u++) {
            uint2 b = __ldg(&bfrag[(size_t)(ks * 16 + warp_n * 4 + u) * 32 + lane]);
            mma_bf16(d[0][u], a[0], b.x, b.y);
            mma_bf16(d[1][u], a[1], b.x, b.y);
        }
    }

    // ---- epilogue: bias + relu + cross-warp row norm ----
    float2 bb[4];
    #pragma unroll
    for (int u = 0; u < 4; u++)
        bb[u] = *(const float2*)(bias + warp_n * 32 + u * 8 + (lane & 3) * 2);

    #pragma unroll
    for (int t = 0; t < 2; t++) {
        float ss0 = 0, ss1 = 0;
        #pragma unroll
        for (int u = 0; u < 4; u++) {
            float c0 = fmaxf(d[t][u][0] + bb[u].x, 0.0f);
            float c1 = fmaxf(d[t][u][1] + bb[u].y, 0.0f);
            float c2 = fmaxf(d[t][u][2] + bb[u].x, 0.0f);
            float c3 = fmaxf(d[t][u][3] + bb[u].y, 0.0f);
            ss0 += c0 * c0 + c1 * c1;
            ss1 += c2 * c2 + c3 * c3;
            d[t][u][0] = c0; d[t][u][1] = c1; d[t][u][2] = c2; d[t][u][3] = c3;
        }
        int lr = (warp_m * 2 + t) * 16 + (lane >> 2);
        atomicAdd(&rowss[lr], ss0);
        atomicAdd(&rowss[lr + 8], ss1);
    }
    __syncthreads();   // rowss ready; all ldmatrix reads complete

    // ---- normalize -> bf16x2 restage into smA (reused as [64][PITCH32] u32) ----
    #pragma unroll
    for (int t = 0; t < 2; t++) {
        int r1 = (warp_m * 2 + t) * 16 + (lane >> 2);
        float rn0 = rsqrtf(rowss[r1]);
        float rn1 = rsqrtf(rowss[r1 + 8]);
        #pragma unroll
        for (int u = 0; u < 4; u++) {
            int cp = warp_n * 16 + u * 4 + (lane & 3);
            smA[r1 * PITCH32 + cp]       = packbf2(d[t][u][0] * rn0, d[t][u][1] * rn0);
            smA[(r1 + 8) * PITCH32 + cp] = packbf2(d[t][u][2] * rn1, d[t][u][3] * rn1);
        }
    }
    __syncthreads();

    // ---- coalesced bf16 dump ----
    #pragma unroll
    for (int e = 0; e < 16; e++) {
        int p = tid + e * 256;
        int r = p >> 6, cp = p & 63;
        int node = n0 + r;
        if (node >= n) continue;
        houtb[(size_t)node * 64 + cp] = smA[r * PITCH32 + cp];
    }
}

// ---------------- cluster mean from bf16 h2: warp per cluster -------------------
__global__ void xc_kernel(const uint2* __restrict__ h2b, int n, int E, int Cc) {
    int w = (int)(((unsigned)blockIdx.x * blockDim.x + threadIdx.x) >> 5);
    if (w >= Cc) return;
    int lane = threadIdx.x & 31;
    int mb = g_off[n + w] - E, me = g_off[n + w + 1] - E;
    float4 acc = make_float4(0, 0, 0, 0);
    int mi = mb;
    for (; mi + 2 <= me; mi += 2) {
        int n0 = g_cnodes[mi], n1 = g_cnodes[mi + 1];
        uint2 u0 = __ldg(h2b + (size_t)n0 * 32 + lane);
        uint2 u1 = __ldg(h2b + (size_t)n1 * 32 + lane);
        bf16acc(acc, u0);
        bf16acc(acc, u1);
    }
    if (mi < me) {
        int n0 = g_cnodes[mi];
        bf16acc(acc, __ldg(h2b + (size_t)n0 * 32 + lane));
    }
    float inv = (me > mb) ? 1.0f / (float)(me - mb) : 0.0f;
    acc.x *= inv; acc.y *= inv; acc.z *= inv; acc.w *= inv;
    *(float4*)(g_xc + (size_t)w * HID + lane * 4) = acc;
    *(uint2*)&g_xcb[(size_t)w * 64 + lane * 2] = packbf(acc);
}

// ---------------- fused cluster layer: SMEM-hash dedup + MLP-4 gather -----------
__global__ __launch_bounds__(256) void cluster_fused_kernel(
    const float* __restrict__ Wl, const float* __restrict__ Wr,
    const float* __restrict__ b, const int* __restrict__ ca,
    const int* __restrict__ bp, int n, int E, int Cc)
{
    __shared__ float WlS[HID * CLS];
    __shared__ float WrS[HID * CLS];
    __shared__ float bS[CLS];
    __shared__ int hsh[8][512];

    int tid = threadIdx.x;
    int lane = tid & 31, wid = tid >> 5;

    for (int i = tid; i < HID * CLS; i += blockDim.x) {
        WlS[i] = Wl[i];
        WrS[i] = Wr[i];
    }
    if (tid < CLS) bS[tid] = b[tid];
    for (int i = lane; i < 512; i += 32) hsh[wid][i] = 0;
    __syncthreads();

    int w = (int)(((unsigned)blockIdx.x * blockDim.x + tid) >> 5);
    if (w >= Cc) return;

    const uint2* xcb = (const uint2*)g_xcb;
    float4 acc = make_float4(0, 0, 0, 0);
    int nuniq = 0;
    int mb = g_off[n + w] - E, me = g_off[n + w + 1] - E;
    for (int mi = mb; mi < me; mi++) {
        int node = g_cnodes[mi];
        int eb = g_off[node], ee = g_off[node + 1];
        for (int j0 = eb; j0 < ee; j0 += 32) {
            int j = j0 + lane;
            int isnew = 0, cu = 0;
            if (j < ee) {
                int s = g_esrt[j];
                cu = __ldg(ca + s);
                int key = cu + 1;
                unsigned h = ((unsigned)cu * 2654435761u) >> 23;
                h &= 511;
                while (true) {
                    int old = atomicCAS(&hsh[wid][h], 0, key);
                    if (old == 0) { isnew = 1; break; }
                    if (old == key) break;
                    h = (h + 1) & 511;
                }
            }
            unsigned m = __ballot_sync(0xffffffffu, isnew);
            nuniq += __popc(m);
            while (m) {
                int b0 = __ffs(m) - 1;             m &= m - 1;
                int b1 = m ? __ffs(m) - 1 : 32; if (b1 < 32) m &= m - 1;
                int b2 = m ? __ffs(m) - 1 : 32; if (b2 < 32) m &= m - 1;
                int b3 = m ? __ffs(m) - 1 : 32; if (b3 < 32) m &= m - 1;
                int c0 = __shfl_sync(0xffffffffu, cu, b0);
                int c1 = __shfl_sync(0xffffffffu, cu, b1 & 31);
                int c2 = __shfl_sync(0xffffffffu, cu, b2 & 31);
                int c3 = __shfl_sync(0xffffffffu, cu, b3 & 31);
                uint2 u0 = __ldg(xcb + (size_t)c0 * 32 + lane);
                uint2 u1 = make_uint2(0, 0), u2 = make_uint2(0, 0), u3 = make_uint2(0, 0);
                if (b1 < 32) u1 = __ldg(xcb + (size_t)c1 * 32 + lane);
                if (b2 < 32) u2 = __ldg(xcb + (size_t)c2 * 32 + lane);
                if (b3 < 32) u3 = __ldg(xcb + (size_t)c3 * 32 + lane);
                bf16acc(acc, u0);
                if (b1 < 32) bf16acc(acc, u1);
                if (b2 < 32) bf16acc(acc, u2);
                if (b3 < 32) bf16acc(acc, u3);
            }
        }
    }
    float inv = nuniq > 0 ? 1.0f / (float)nuniq : 0.0f;
    float4 a = make_float4(acc.x * inv, acc.y * inv, acc.z * inv, acc.w * inv);
    float4 xv = *(const float4*)(g_xc + (size_t)w * HID + lane * 4);

    float c[CLS];
    int k0 = lane * 4;
    #pragma unroll
    for (int j = 0; j < CLS; j++) {
        float s = a.x * WlS[(k0 + 0) * CLS + j] + xv.x * WrS[(k0 + 0) * CLS + j];
        s += a.y * WlS[(k0 + 1) * CLS + j] + xv.y * WrS[(k0 + 1) * CLS + j];
        s += a.z * WlS[(k0 + 2) * CLS + j] + xv.z * WrS[(k0 + 2) * CLS + j];
        s += a.w * WlS[(k0 + 3) * CLS + j] + xv.w * WrS[(k0 + 3) * CLS + j];
        c[j] = s;
    }
    #pragma unroll
    for (int j = 0; j < CLS; j++) {
        #pragma unroll
        for (int off = 16; off; off >>= 1)
            c[j] += __shfl_xor_sync(0xffffffffu, c[j], off);
    }
    float ss = 0.0f;
    #pragma unroll
    for (int j = 0; j < CLS; j++) { c[j] += bS[j]; ss += c[j] * c[j]; }
    float rn = rsqrtf(ss);
    int g = __ldg(bp + w);
    if (lane < CLS) atomicAdd(&Zgsum[g * CLS + lane], c[lane] * rn);
    if (lane == 0) atomicAdd(&Zgcnt[g], 1);
}

__global__ void final_kernel(float* __restrict__ out, int G) {
    int g = blockIdx.x * blockDim.x + threadIdx.x;
    if (g >= G) return;
    int cnt = Zgcnt[g];
    float inv = cnt > 0 ? 1.0f / (float)cnt : 0.0f;
    float v[CLS];
    float mx = -1e30f;
    #pragma unroll
    for (int j = 0; j < CLS; j++) { v[j] = Zgsum[g * CLS + j] * inv; mx = fmaxf(mx, v[j]); }
    float s = 0.0f;
    #pragma unroll
    for (int j = 0; j < CLS; j++) s += expf(v[j] - mx);
    float lse = logf(s) + mx;
    #pragma unroll
    for (int j = 0; j < CLS; j++) out[g * CLS + j] = v[j] - lse;
}

// ---------------- launch ---------------------------------------------------------
extern "C" void kernel_launch(void* const* d_in, const int* in_sizes, int n_in,
                              void* d_out, int out_size) {
    const float* x     = (const float*)d_in[0];
    const float* Wl_in = (const float*)d_in[1];
    const float* Wr_in = (const float*)d_in[2];
    const float* b_in  = (const float*)d_in[3];
    const float* Wl_h  = (const float*)d_in[4];
    const float* Wr_h  = (const float*)d_in[5];
    const float* b_h   = (const float*)d_in[6];
    const float* Wl_o  = (const float*)d_in[7];
    const float* Wr_o  = (const float*)d_in[8];
    const float* b_o   = (const float*)d_in[9];
    const int* esrc = (const int*)d_in[10];
    const int* edst = (const int*)d_in[11];
    const int* ca   = (const int*)d_in[12];
    const int* bp   = (const int*)d_in[13];

    int n  = in_sizes[0] / HID;
    int E  = in_sizes[10];
    int Cc = in_sizes[13];
    int G  = out_size / CLS;
    int m  = n + Cc;
    float* out = (float*)d_out;

    void *p_zero, *p_off, *p_cur, *p_xb, *p_h1b, *p_h2b, *p_aggb, *p_bfrag;
    cudaGetSymbolAddress(&p_zero,  g_zero);
    cudaGetSymbolAddress(&p_off,   g_off);
    cudaGetSymbolAddress(&p_cur,   g_cur);
    cudaGetSymbolAddress(&p_xb,    g_xb);
    cudaGetSymbolAddress(&p_h1b,   g_h1b);
    cudaGetSymbolAddress(&p_h2b,   g_h2b);
    cudaGetSymbolAddress(&p_aggb,  g_aggb);
    cudaGetSymbolAddress(&p_bfrag, g_bfrag);

    cudaMemsetAsync(p_zero, 0, (size_t)ZTOTAL * sizeof(int));

    int pthreads = NBFRAG + n * 32;
    if (pthreads < E) pthreads = E;
    prep_count_kernel<<<(pthreads + 255) / 256, 256>>>(
        edst, ca, Wl_in, Wr_in, Wl_h, Wr_h, x, (uint2*)p_xb, E, n);

    int nb = (m + SCAN_B - 1) / SCAN_B;
    scan_lookback<<<nb, SCAN_B>>>((const int*)p_zero, (int*)p_off, (int*)p_cur, m);

    int half = (E + 1) / 2;
    int cover = (half > n) ? half : n;
    fill_kernel<<<(cover + 255) / 256, 256>>>(esrc, edst, ca, E, half, n);

    const uint2* bfrag = (const uint2*)p_bfrag;
    int tiles = (n + 63) / 64;
    int gwb = (n + 15) / 16;

    // layer 1
    gather_kernel<<<gwb, 512>>>((const uint2*)p_xb, (uint2*)p_aggb, n);
    gemm_layer<<<tiles, 256>>>(
        (const uint2*)p_aggb, (const uint2*)p_xb, bfrag, b_in, (uint32_t*)p_h1b, n);
    // layer 2
    gather_kernel<<<gwb, 512>>>((const uint2*)p_h1b, (uint2*)p_aggb, n);
    gemm_layer<<<tiles, 256>>>(
        (const uint2*)p_aggb, (const uint2*)p_h1b, bfrag + 16 * 16 * 32, b_h,
        (uint32_t*)p_h2b, n);

    xc_kernel<<<(Cc + 7) / 8, 256>>>((const uint2*)p_h2b, n, E, Cc);
    cluster_fused_kernel<<<(Cc + 7) / 8, 256>>>(Wl_o, Wr_o, b_o, ca, bp, n, E, Cc);

    final_kernel<<<(G + 63) / 64, 64>>>(out, G);
}